// round 7
// baseline (speedup 1.0000x reference)
#include <cuda_runtime.h>
#include <math.h>
#include <stdint.h>

#define SS 2048
#define DD 512
#define NB 4
#define KC 32
#define NTHREADS 128                    // 4 warps, 2x2 warp grid, warp tile 64x64
#define LDSW 36                         // smem row stride in floats (bank-conflict-free)
#define STAGE_U32 (2 * 128 * LDSW)      // X tile + Y tile
#define SMEM_DYN  (2 * STAGE_U32 * 4)   // 2 stages, bytes (73728)

// ---------------- scratch (allocation-free device globals) ----------------
__device__ float g_W[(size_t)NB * SS * SS];    // 64 MB weight matrix
__device__ float g_VT[(size_t)NB * DD * SS];   // 16 MB V transposed [n][k]
__device__ float g_l1[NB * SS];
__device__ float g_m2[NB * SS];
__device__ float g_v2[NB * SS];

// ---------------- helpers ----------------
__device__ __forceinline__ uint32_t f2tf32(float x) {
    uint32_t r;
    asm("cvt.rna.tf32.f32 %0, %1;" : "=r"(r) : "f"(x));
    return r;
}
__device__ __forceinline__ void mma_tf32(float* c, const uint32_t* a, const uint32_t* b) {
    asm volatile(
        "mma.sync.aligned.m16n8k8.row.col.f32.tf32.tf32.f32 "
        "{%0,%1,%2,%3}, {%4,%5,%6,%7}, {%8,%9}, {%0,%1,%2,%3};"
        : "+f"(c[0]), "+f"(c[1]), "+f"(c[2]), "+f"(c[3])
        : "r"(a[0]), "r"(a[1]), "r"(a[2]), "r"(a[3]), "r"(b[0]), "r"(b[1]));
}

// ---------------------------------------------------------------------------
// Stage a 128x32 K-major tile of X and of Y into smem as rna-rounded tf32.
// 128 threads: 8 float4 per thread per tile.
// ---------------------------------------------------------------------------
__device__ __forceinline__ void stage_load(const float* __restrict__ X,
                                           const float* __restrict__ Y,
                                           int ldx, int ldy, int m0, int n0, int k0,
                                           uint32_t* __restrict__ st, int tid) {
    uint32_t* xs = st;
    uint32_t* ys = st + 128 * LDSW;
#pragma unroll
    for (int p = 0; p < 8; ++p) {
        int idx = tid + p * NTHREADS;
        int row = idx >> 3, kq = (idx & 7) << 2;
        float4 v = *reinterpret_cast<const float4*>(
            X + (size_t)(m0 + row) * ldx + k0 + kq);
        uint4 t = make_uint4(f2tf32(v.x), f2tf32(v.y), f2tf32(v.z), f2tf32(v.w));
        *reinterpret_cast<uint4*>(xs + row * LDSW + kq) = t;
    }
#pragma unroll
    for (int p = 0; p < 8; ++p) {
        int idx = tid + p * NTHREADS;
        int row = idx >> 3, kq = (idx & 7) << 2;
        float4 v = *reinterpret_cast<const float4*>(
            Y + (size_t)(n0 + row) * ldy + k0 + kq);
        uint4 t = make_uint4(f2tf32(v.x), f2tf32(v.y), f2tf32(v.z), f2tf32(v.w));
        *reinterpret_cast<uint4*>(ys + row * LDSW + kq) = t;
    }
}

// ---------------------------------------------------------------------------
// One KC=32 chunk. Warp tile 64(m) x 64(n): 4 m-frags x 8 n-frags = 32 mma/ks.
// Fragment layout (m16n8k8 tf32): g = lane>>2, tg = lane&3.
// ---------------------------------------------------------------------------
__device__ __forceinline__ void compute_chunk(const uint32_t* __restrict__ st,
                                              float acc[4][8][4],
                                              int wm, int wn, int g, int tg) {
    const uint32_t* xs = st;
    const uint32_t* ys = st + 128 * LDSW;
#pragma unroll
    for (int ks = 0; ks < 4; ++ks) {
        int kk = ks * 8;
        uint32_t af[4][4], bf[8][2];
#pragma unroll
        for (int mf = 0; mf < 4; ++mf) {
            int rb = wm * 64 + mf * 16;
            af[mf][0] = xs[(rb + g) * LDSW + kk + tg];
            af[mf][1] = xs[(rb + 8 + g) * LDSW + kk + tg];
            af[mf][2] = xs[(rb + g) * LDSW + kk + tg + 4];
            af[mf][3] = xs[(rb + 8 + g) * LDSW + kk + tg + 4];
        }
#pragma unroll
        for (int nf = 0; nf < 8; ++nf) {
            int nb = wn * 64 + nf * 8;
            bf[nf][0] = ys[(nb + g) * LDSW + kk + tg];
            bf[nf][1] = ys[(nb + g) * LDSW + kk + tg + 4];
        }
#pragma unroll
        for (int mf = 0; mf < 4; ++mf)
#pragma unroll
            for (int nf = 0; nf < 8; ++nf)
                mma_tf32(acc[mf][nf], af[mf], bf[nf]);
    }
}

// ---------------------------------------------------------------------------
// Double-buffered mainloop: acc += X[m0:m0+128,:] @ Y[n0:n0+128,:]^T, K=nch*KC.
// ---------------------------------------------------------------------------
__device__ __forceinline__ void mainloop(const float* X, const float* Y,
                                         int ldx, int ldy, int nch,
                                         int m0, int n0, uint32_t* dyn,
                                         float acc[4][8][4],
                                         int tid, int wm, int wn, int g, int tg) {
    stage_load(X, Y, ldx, ldy, m0, n0, 0, dyn, tid);
    __syncthreads();
    for (int ch = 0; ch < nch; ++ch) {
        if (ch + 1 < nch)
            stage_load(X, Y, ldx, ldy, m0, n0, (ch + 1) * KC,
                       dyn + ((ch + 1) & 1) * STAGE_U32, tid);
        compute_chunk(dyn + (ch & 1) * STAGE_U32, acc, wm, wn, g, tg);
        __syncthreads();
    }
}

// ---------------------------------------------------------------------------
// Row squared-norms; which=0 -> g_v2, which=1 -> g_m2 + zero g_l1.
// ---------------------------------------------------------------------------
__global__ void rownorm_kernel(const float* __restrict__ X, int which) {
    int row = blockIdx.x;
    const float4* xp = reinterpret_cast<const float4*>(X + (size_t)row * DD);
    float4 v = xp[threadIdx.x];
    float s = v.x * v.x + v.y * v.y + v.z * v.z + v.w * v.w;
#pragma unroll
    for (int o = 16; o > 0; o >>= 1) s += __shfl_down_sync(0xffffffffu, s, o);
    __shared__ float ws[4];
    if ((threadIdx.x & 31) == 0) ws[threadIdx.x >> 5] = s;
    __syncthreads();
    if (threadIdx.x == 0) {
        float tot = ws[0] + ws[1] + ws[2] + ws[3];
        if (which) { g_m2[row] = tot; g_l1[row] = 0.0f; }
        else       { g_v2[row] = tot; }
    }
}

// ---------------------------------------------------------------------------
// VT[b][n][k] = V[b][k][n]   (32x32 smem transpose tiles)
// ---------------------------------------------------------------------------
__global__ void transpose_kernel(const float* __restrict__ V) {
    __shared__ float t[32][33];
    int b = blockIdx.z;
    const float* Vp = V + (size_t)b * SS * DD;
    float* Tp = g_VT + (size_t)b * DD * SS;
    int x0 = blockIdx.x * 32;  // n
    int y0 = blockIdx.y * 32;  // k
    int tx = threadIdx.x & 31, ty = threadIdx.x >> 5;
#pragma unroll
    for (int i = ty; i < 32; i += 8)
        t[i][tx] = Vp[(size_t)(y0 + i) * DD + x0 + tx];
    __syncthreads();
#pragma unroll
    for (int i = ty; i < 32; i += 8)
        Tp[(size_t)(x0 + i) * SS + y0 + tx] = t[tx][i];
}

// ---------------------------------------------------------------------------
// GEMM: C[m, n] = scale(m) * sum_k Xop[m,k] * VT[n,k]   (N = DD = 512)
// use_w: Xop = g_W.  use_l1: scale = 1/max(l1[m], 1e-12).
// ---------------------------------------------------------------------------
__global__ void __launch_bounds__(NTHREADS, 2)
gemm_tc(const float* __restrict__ Aext, float* __restrict__ C,
        int use_w, int use_l1) {
    extern __shared__ uint32_t dyn[];
    int tid = threadIdx.x;
    int wid = tid >> 5, lane = tid & 31;
    int wm = wid >> 1, wn = wid & 1;
    int g = lane >> 2, tg = lane & 3;
    int b = blockIdx.z;
    int n0 = blockIdx.x * 128, m0 = blockIdx.y * 128;
    const float* X = (use_w ? g_W : Aext) + (size_t)b * SS * SS;
    const float* Y = g_VT + (size_t)b * DD * SS;
    C += (size_t)b * SS * DD;

    float acc[4][8][4];
#pragma unroll
    for (int i = 0; i < 4; ++i)
#pragma unroll
        for (int j = 0; j < 8; ++j)
#pragma unroll
            for (int e = 0; e < 4; ++e) acc[i][j][e] = 0.0f;

    mainloop(X, Y, SS, SS, SS / KC, m0, n0, dyn, acc, tid, wm, wn, g, tg);

#pragma unroll
    for (int mf = 0; mf < 4; ++mf) {
        int r1 = m0 + wm * 64 + mf * 16 + g;
        int r2 = r1 + 8;
        float s1 = 1.0f, s2 = 1.0f;
        if (use_l1) {
            s1 = 1.0f / fmaxf(g_l1[b * SS + r1], 1e-12f);
            s2 = 1.0f / fmaxf(g_l1[b * SS + r2], 1e-12f);
        }
#pragma unroll
        for (int nf = 0; nf < 8; ++nf) {
            int col = n0 + wn * 64 + nf * 8 + 2 * tg;
            float2 o1 = make_float2(acc[mf][nf][0] * s1, acc[mf][nf][1] * s1);
            float2 o2 = make_float2(acc[mf][nf][2] * s2, acc[mf][nf][3] * s2);
            *reinterpret_cast<float2*>(C + (size_t)r1 * DD + col) = o1;
            *reinterpret_cast<float2*>(C + (size_t)r2 * DD + col) = o2;
        }
    }
}

// ---------------------------------------------------------------------------
// W[i,j] = A[i,j] / (sqrt(max(m2[i]+v2[j]-2*M_i.V_j, 0)) + 0.01) + l1 row sums.
// ---------------------------------------------------------------------------
__global__ void __launch_bounds__(NTHREADS, 2)
wdist_tc(const float* __restrict__ M, const float* __restrict__ V,
         const float* __restrict__ A) {
    extern __shared__ uint32_t dyn[];
    int tid = threadIdx.x;
    int wid = tid >> 5, lane = tid & 31;
    int wm = wid >> 1, wn = wid & 1;
    int g = lane >> 2, tg = lane & 3;
    int b = blockIdx.z;
    int j0 = blockIdx.x * 128, i0 = blockIdx.y * 128;
    const float* Mp = M + (size_t)b * SS * DD;
    const float* Vp = V + (size_t)b * SS * DD;
    const float* Ap = A + (size_t)b * SS * SS;
    float* Wp = g_W + (size_t)b * SS * SS;
    const float* v2p = g_v2 + b * SS;

    float acc[4][8][4];
#pragma unroll
    for (int i = 0; i < 4; ++i)
#pragma unroll
        for (int j = 0; j < 8; ++j)
#pragma unroll
            for (int e = 0; e < 4; ++e) acc[i][j][e] = 0.0f;

    mainloop(Mp, Vp, DD, DD, DD / KC, i0, j0, dyn, acc, tid, wm, wn, g, tg);

#pragma unroll
    for (int mf = 0; mf < 4; ++mf) {
        int r1 = i0 + wm * 64 + mf * 16 + g;
        int r2 = r1 + 8;
        float m21 = g_m2[b * SS + r1];
        float m22 = g_m2[b * SS + r2];
        float rs1 = 0.0f, rs2 = 0.0f;
#pragma unroll
        for (int nf = 0; nf < 8; ++nf) {
            int jj = j0 + wn * 64 + nf * 8 + 2 * tg;
            float v2a = v2p[jj], v2b = v2p[jj + 1];
            float2 a1 = *reinterpret_cast<const float2*>(Ap + (size_t)r1 * SS + jj);
            float2 a2 = *reinterpret_cast<const float2*>(Ap + (size_t)r2 * SS + jj);
            float d;
            d = sqrtf(fmaxf(m21 + v2a - 2.0f * acc[mf][nf][0], 0.0f));
            float w0 = a1.x * __frcp_rn(d + 0.01f);
            d = sqrtf(fmaxf(m21 + v2b - 2.0f * acc[mf][nf][1], 0.0f));
            float w1 = a1.y * __frcp_rn(d + 0.01f);
            d = sqrtf(fmaxf(m22 + v2a - 2.0f * acc[mf][nf][2], 0.0f));
            float w2 = a2.x * __frcp_rn(d + 0.01f);
            d = sqrtf(fmaxf(m22 + v2b - 2.0f * acc[mf][nf][3], 0.0f));
            float w3 = a2.y * __frcp_rn(d + 0.01f);
            rs1 += fabsf(w0) + fabsf(w1);
            rs2 += fabsf(w2) + fabsf(w3);
            *reinterpret_cast<float2*>(Wp + (size_t)r1 * SS + jj) = make_float2(w0, w1);
            *reinterpret_cast<float2*>(Wp + (size_t)r2 * SS + jj) = make_float2(w2, w3);
        }
        // reduce across the quad (lanes differing in tg only)
        rs1 += __shfl_xor_sync(0xffffffffu, rs1, 1);
        rs1 += __shfl_xor_sync(0xffffffffu, rs1, 2);
        rs2 += __shfl_xor_sync(0xffffffffu, rs2, 1);
        rs2 += __shfl_xor_sync(0xffffffffu, rs2, 2);
        if (tg == 0) {
            atomicAdd(&g_l1[b * SS + r1], rs1);
            atomicAdd(&g_l1[b * SS + r2], rs2);
        }
    }
}

// ---------------------------------------------------------------------------
extern "C" void kernel_launch(void* const* d_in, const int* in_sizes, int n_in,
                              void* d_out, int out_size) {
    const float* A = (const float*)d_in[0];  // (4, 2048, 2048)
    const float* V = (const float*)d_in[1];  // (4, 2048, 512)
    float* M = (float*)d_out;                // (4, 2048, 512)

    cudaFuncSetAttribute(gemm_tc, cudaFuncAttributeMaxDynamicSharedMemorySize, SMEM_DYN);
    cudaFuncSetAttribute(wdist_tc, cudaFuncAttributeMaxDynamicSharedMemorySize, SMEM_DYN);

    dim3 ggrid(DD / 128, SS / 128, NB);  // (4, 16, 4)
    dim3 wgrid(SS / 128, SS / 128, NB);  // (16, 16, 4)

    transpose_kernel<<<dim3(DD / 32, SS / 32, NB), 256>>>(V);
    rownorm_kernel<<<NB * SS, 128>>>(V, 0);
    gemm_tc<<<ggrid, NTHREADS, SMEM_DYN>>>(A, M, 0, 0);
    for (int it = 0; it < 3; ++it) {
        rownorm_kernel<<<NB * SS, 128>>>(M, 1);
        wdist_tc<<<wgrid, NTHREADS, SMEM_DYN>>>(M, V, A);
        gemm_tc<<<ggrid, NTHREADS, SMEM_DYN>>>(nullptr, M, 1, 1);
    }
}

// round 8
// speedup vs baseline: 1.6886x; 1.6886x over previous
#include <cuda_runtime.h>
#include <math.h>
#include <stdint.h>

#define SS 2048
#define DD 512
#define NB 4
#define KC 32
#define NTHREADS 256                    // 8 warps, 2x4 grid, warp tile 64x32
#define LDSW 36                         // smem row stride in floats (conflict-free)
#define STAGE_U32 (2 * 128 * LDSW)      // X tile + Y tile per stage
#define STAGE_BYTES (STAGE_U32 * 4)     // 36864
#define NSTAGE 3
#define SMEM_DYN (NSTAGE * STAGE_BYTES) // 110592

// ---------------- scratch (allocation-free device globals) ----------------
__device__ float g_W[(size_t)NB * SS * SS];    // 64 MB rounded weight matrix
__device__ float g_At[(size_t)NB * SS * SS];   // 64 MB rounded A
__device__ float g_Vt[(size_t)NB * SS * DD];   // 16 MB rounded V
__device__ float g_VTt[(size_t)NB * DD * SS];  // 16 MB rounded V^T [n][k]
__device__ float g_Mt[(size_t)NB * SS * DD];   // 16 MB rounded M
__device__ float g_l1[NB * SS];
__device__ float g_m2[NB * SS];
__device__ float g_v2[NB * SS];

// ---------------- helpers ----------------
__device__ __forceinline__ float f2tf32f(float x) {
    uint32_t r;
    asm("cvt.rna.tf32.f32 %0, %1;" : "=r"(r) : "f"(x));
    return __uint_as_float(r);
}
__device__ __forceinline__ uint32_t smem_u32(const void* p) {
    uint32_t a;
    asm("{ .reg .u64 t; cvta.to.shared.u64 t, %1; cvt.u32.u64 %0, t; }"
        : "=r"(a) : "l"(p));
    return a;
}
__device__ __forceinline__ void cp16(uint32_t saddr, const void* gaddr) {
    asm volatile("cp.async.cg.shared.global [%0], [%1], 16;"
                 :: "r"(saddr), "l"(gaddr) : "memory");
}
__device__ __forceinline__ void cp_commit() {
    asm volatile("cp.async.commit_group;" ::: "memory");
}
template <int N>
__device__ __forceinline__ void cp_wait() {
    asm volatile("cp.async.wait_group %0;" :: "n"(N) : "memory");
}
__device__ __forceinline__ void mma_tf32(float* c, const uint32_t* a, const uint32_t* b) {
    asm volatile(
        "mma.sync.aligned.m16n8k8.row.col.f32.tf32.tf32.f32 "
        "{%0,%1,%2,%3}, {%4,%5,%6,%7}, {%8,%9}, {%0,%1,%2,%3};"
        : "+f"(c[0]), "+f"(c[1]), "+f"(c[2]), "+f"(c[3])
        : "r"(a[0]), "r"(a[1]), "r"(a[2]), "r"(a[3]), "r"(b[0]), "r"(b[1]));
}

// ---------------------------------------------------------------------------
// Issue one stage: 128x32 X tile + 128x32 Y tile via cp.async (data already
// tf32-rounded in gmem). 8 x 16B per thread. Commits one group.
// ---------------------------------------------------------------------------
__device__ __forceinline__ void issue_stage(const float* __restrict__ X,
                                            const float* __restrict__ Y,
                                            int ldx, int ldy, int m0, int n0,
                                            int k0, uint32_t sbuf, int tid) {
#pragma unroll
    for (int p = 0; p < 4; ++p) {
        int idx = tid + p * NTHREADS;
        int row = idx >> 3, kq = (idx & 7) << 2;
        cp16(sbuf + (row * LDSW + kq) * 4,
             X + (size_t)(m0 + row) * ldx + k0 + kq);
    }
    uint32_t ybuf = sbuf + 128 * LDSW * 4;
#pragma unroll
    for (int p = 0; p < 4; ++p) {
        int idx = tid + p * NTHREADS;
        int row = idx >> 3, kq = (idx & 7) << 2;
        cp16(ybuf + (row * LDSW + kq) * 4,
             Y + (size_t)(n0 + row) * ldy + k0 + kq);
    }
    cp_commit();
}

// ---------------------------------------------------------------------------
// One KC=32 chunk. Warp tile 64(m) x 32(n): 4 m-frags x 4 n-frags.
// Fragment layout (m16n8k8 tf32): g = lane>>2, tg = lane&3.
// ---------------------------------------------------------------------------
__device__ __forceinline__ void compute_chunk(const uint32_t* __restrict__ st,
                                              float acc[4][4][4],
                                              int wm, int wn, int g, int tg) {
    const uint32_t* xs = st;
    const uint32_t* ys = st + 128 * LDSW;
#pragma unroll
    for (int ks = 0; ks < 4; ++ks) {
        int kk = ks * 8;
        uint32_t af[4][4], bf[4][2];
#pragma unroll
        for (int mf = 0; mf < 4; ++mf) {
            int rb = wm * 64 + mf * 16;
            af[mf][0] = xs[(rb + g) * LDSW + kk + tg];
            af[mf][1] = xs[(rb + 8 + g) * LDSW + kk + tg];
            af[mf][2] = xs[(rb + g) * LDSW + kk + tg + 4];
            af[mf][3] = xs[(rb + 8 + g) * LDSW + kk + tg + 4];
        }
#pragma unroll
        for (int nf = 0; nf < 4; ++nf) {
            int nb = wn * 32 + nf * 8;
            bf[nf][0] = ys[(nb + g) * LDSW + kk + tg];
            bf[nf][1] = ys[(nb + g) * LDSW + kk + tg + 4];
        }
#pragma unroll
        for (int mf = 0; mf < 4; ++mf)
#pragma unroll
            for (int nf = 0; nf < 4; ++nf)
                mma_tf32(acc[mf][nf], af[mf], bf[nf]);
    }
}

// ---------------------------------------------------------------------------
// 3-stage cp.async mainloop: acc += X[m0:+128,:] @ Y[n0:+128,:]^T, K=nch*KC.
// ---------------------------------------------------------------------------
__device__ __forceinline__ void mainloop(const float* X, const float* Y,
                                         int ldx, int ldy, int nch,
                                         int m0, int n0, uint32_t* dyn,
                                         float acc[4][4][4],
                                         int tid, int wm, int wn, int g, int tg) {
    uint32_t sb = smem_u32(dyn);
#pragma unroll
    for (int s = 0; s < NSTAGE; ++s)
        issue_stage(X, Y, ldx, ldy, m0, n0, s * KC, sb + s * STAGE_BYTES, tid);
    for (int ch = 0; ch < nch; ++ch) {
        cp_wait<NSTAGE - 1>();
        __syncthreads();
        compute_chunk(dyn + (ch % NSTAGE) * STAGE_U32, acc, wm, wn, g, tg);
        __syncthreads();
        if (ch + NSTAGE < nch)
            issue_stage(X, Y, ldx, ldy, m0, n0, (ch + NSTAGE) * KC,
                        sb + (ch % NSTAGE) * STAGE_BYTES, tid);
    }
}

// ---------------------------------------------------------------------------
// Elementwise rna-round to tf32 bits (grid-stride, float4).
// ---------------------------------------------------------------------------
__global__ void round_kernel(const float* __restrict__ in, float* __restrict__ out,
                             int n4) {
    int i = blockIdx.x * blockDim.x + threadIdx.x;
    int stride = gridDim.x * blockDim.x;
    for (; i < n4; i += stride) {
        float4 v = reinterpret_cast<const float4*>(in)[i];
        v.x = f2tf32f(v.x); v.y = f2tf32f(v.y); v.z = f2tf32f(v.z); v.w = f2tf32f(v.w);
        reinterpret_cast<float4*>(out)[i] = v;
    }
}

// ---------------------------------------------------------------------------
// Row squared-norms of rounded input; which=0 -> g_v2, which=1 -> g_m2+zero l1.
// ---------------------------------------------------------------------------
__global__ void rownorm_kernel(const float* __restrict__ X, int which) {
    int row = blockIdx.x;
    const float4* xp = reinterpret_cast<const float4*>(X + (size_t)row * DD);
    float4 v = xp[threadIdx.x];
    float s = v.x * v.x + v.y * v.y + v.z * v.z + v.w * v.w;
#pragma unroll
    for (int o = 16; o > 0; o >>= 1) s += __shfl_down_sync(0xffffffffu, s, o);
    __shared__ float ws[4];
    if ((threadIdx.x & 31) == 0) ws[threadIdx.x >> 5] = s;
    __syncthreads();
    if (threadIdx.x == 0) {
        float tot = ws[0] + ws[1] + ws[2] + ws[3];
        if (which) { g_m2[row] = tot; g_l1[row] = 0.0f; }
        else       { g_v2[row] = tot; }
    }
}

// ---------------------------------------------------------------------------
// g_VTt[b][n][k] = round(V[b][k][n])
// ---------------------------------------------------------------------------
__global__ void transpose_kernel(const float* __restrict__ V) {
    __shared__ float t[32][33];
    int b = blockIdx.z;
    const float* Vp = V + (size_t)b * SS * DD;
    float* Tp = g_VTt + (size_t)b * DD * SS;
    int x0 = blockIdx.x * 32;  // n
    int y0 = blockIdx.y * 32;  // k
    int tx = threadIdx.x & 31, ty = threadIdx.x >> 5;
#pragma unroll
    for (int i = ty; i < 32; i += 8)
        t[i][tx] = f2tf32f(Vp[(size_t)(y0 + i) * DD + x0 + tx]);
    __syncthreads();
#pragma unroll
    for (int i = ty; i < 32; i += 8)
        Tp[(size_t)(x0 + i) * SS + y0 + tx] = t[tx][i];
}

// ---------------------------------------------------------------------------
// GEMM: C[m,n] = scale(m) * sum_k X[m,k]*VTt[n,k];  also writes rounded M.
// use_w: X = g_W.  use_l1: scale = 1/max(l1[m],1e-12).
// ---------------------------------------------------------------------------
__global__ void __launch_bounds__(NTHREADS, 2)
gemm_tc(const float* __restrict__ unused, float* __restrict__ C,
        int use_w, int use_l1) {
    extern __shared__ uint32_t dyn[];
    int tid = threadIdx.x;
    int wid = tid >> 5, lane = tid & 31;
    int wm = wid >> 2, wn = wid & 3;
    int g = lane >> 2, tg = lane & 3;
    int b = blockIdx.z;
    int n0 = blockIdx.x * 128, m0 = blockIdx.y * 128;
    const float* X = (use_w ? g_W : g_At) + (size_t)b * SS * SS;
    const float* Y = g_VTt + (size_t)b * DD * SS;
    C += (size_t)b * SS * DD;
    float* Mt = g_Mt + (size_t)b * SS * DD;

    float acc[4][4][4];
#pragma unroll
    for (int i = 0; i < 4; ++i)
#pragma unroll
        for (int j = 0; j < 4; ++j)
#pragma unroll
            for (int e = 0; e < 4; ++e) acc[i][j][e] = 0.0f;

    mainloop(X, Y, SS, SS, SS / KC, m0, n0, dyn, acc, tid, wm, wn, g, tg);

#pragma unroll
    for (int mf = 0; mf < 4; ++mf) {
        int r1 = m0 + wm * 64 + mf * 16 + g;
        int r2 = r1 + 8;
        float s1 = 1.0f, s2 = 1.0f;
        if (use_l1) {
            s1 = 1.0f / fmaxf(g_l1[b * SS + r1], 1e-12f);
            s2 = 1.0f / fmaxf(g_l1[b * SS + r2], 1e-12f);
        }
#pragma unroll
        for (int nf = 0; nf < 4; ++nf) {
            int col = n0 + wn * 32 + nf * 8 + 2 * tg;
            float m0v = acc[mf][nf][0] * s1, m1v = acc[mf][nf][1] * s1;
            float m2v = acc[mf][nf][2] * s2, m3v = acc[mf][nf][3] * s2;
            *reinterpret_cast<float2*>(C + (size_t)r1 * DD + col) = make_float2(m0v, m1v);
            *reinterpret_cast<float2*>(C + (size_t)r2 * DD + col) = make_float2(m2v, m3v);
            *reinterpret_cast<float2*>(Mt + (size_t)r1 * DD + col) =
                make_float2(f2tf32f(m0v), f2tf32f(m1v));
            *reinterpret_cast<float2*>(Mt + (size_t)r2 * DD + col) =
                make_float2(f2tf32f(m2v), f2tf32f(m3v));
        }
    }
}

// ---------------------------------------------------------------------------
// W[i,j] = round(A[i,j]/(sqrt(max(m2[i]+v2[j]-2*Mt_i.Vt_j,0))+0.01)); l1 sums.
// ---------------------------------------------------------------------------
__global__ void __launch_bounds__(NTHREADS, 2)
wdist_tc(const float* __restrict__ A) {
    extern __shared__ uint32_t dyn[];
    int tid = threadIdx.x;
    int wid = tid >> 5, lane = tid & 31;
    int wm = wid >> 2, wn = wid & 3;
    int g = lane >> 2, tg = lane & 3;
    int b = blockIdx.z;
    int j0 = blockIdx.x * 128, i0 = blockIdx.y * 128;
    const float* Mp = g_Mt + (size_t)b * SS * DD;
    const float* Vp = g_Vt + (size_t)b * SS * DD;
    const float* Ap = A + (size_t)b * SS * SS;
    float* Wp = g_W + (size_t)b * SS * SS;
    const float* v2p = g_v2 + b * SS;

    float acc[4][4][4];
#pragma unroll
    for (int i = 0; i < 4; ++i)
#pragma unroll
        for (int j = 0; j < 4; ++j)
#pragma unroll
            for (int e = 0; e < 4; ++e) acc[i][j][e] = 0.0f;

    mainloop(Mp, Vp, DD, DD, DD / KC, i0, j0, dyn, acc, tid, wm, wn, g, tg);

#pragma unroll
    for (int mf = 0; mf < 4; ++mf) {
        int r1 = i0 + wm * 64 + mf * 16 + g;
        int r2 = r1 + 8;
        float m21 = g_m2[b * SS + r1];
        float m22 = g_m2[b * SS + r2];
        float rs1 = 0.0f, rs2 = 0.0f;
#pragma unroll
        for (int nf = 0; nf < 4; ++nf) {
            int jj = j0 + wn * 32 + nf * 8 + 2 * tg;
            float v2a = v2p[jj], v2b = v2p[jj + 1];
            float2 a1 = *reinterpret_cast<const float2*>(Ap + (size_t)r1 * SS + jj);
            float2 a2 = *reinterpret_cast<const float2*>(Ap + (size_t)r2 * SS + jj);
            float d;
            d = sqrtf(fmaxf(m21 + v2a - 2.0f * acc[mf][nf][0], 0.0f));
            float w0 = f2tf32f(a1.x * __frcp_rn(d + 0.01f));
            d = sqrtf(fmaxf(m21 + v2b - 2.0f * acc[mf][nf][1], 0.0f));
            float w1 = f2tf32f(a1.y * __frcp_rn(d + 0.01f));
            d = sqrtf(fmaxf(m22 + v2a - 2.0f * acc[mf][nf][2], 0.0f));
            float w2 = f2tf32f(a2.x * __frcp_rn(d + 0.01f));
            d = sqrtf(fmaxf(m22 + v2b - 2.0f * acc[mf][nf][3], 0.0f));
            float w3 = f2tf32f(a2.y * __frcp_rn(d + 0.01f));
            rs1 += fabsf(w0) + fabsf(w1);
            rs2 += fabsf(w2) + fabsf(w3);
            *reinterpret_cast<float2*>(Wp + (size_t)r1 * SS + jj) = make_float2(w0, w1);
            *reinterpret_cast<float2*>(Wp + (size_t)r2 * SS + jj) = make_float2(w2, w3);
        }
        rs1 += __shfl_xor_sync(0xffffffffu, rs1, 1);
        rs1 += __shfl_xor_sync(0xffffffffu, rs1, 2);
        rs2 += __shfl_xor_sync(0xffffffffu, rs2, 1);
        rs2 += __shfl_xor_sync(0xffffffffu, rs2, 2);
        if (tg == 0) {
            atomicAdd(&g_l1[b * SS + r1], rs1);
            atomicAdd(&g_l1[b * SS + r2], rs2);
        }
    }
}

// ---------------------------------------------------------------------------
extern "C" void kernel_launch(void* const* d_in, const int* in_sizes, int n_in,
                              void* d_out, int out_size) {
    const float* A = (const float*)d_in[0];  // (4, 2048, 2048)
    const float* V = (const float*)d_in[1];  // (4, 2048, 512)
    float* M = (float*)d_out;                // (4, 2048, 512)

    cudaFuncSetAttribute(gemm_tc, cudaFuncAttributeMaxDynamicSharedMemorySize, SMEM_DYN);
    cudaFuncSetAttribute(wdist_tc, cudaFuncAttributeMaxDynamicSharedMemorySize, SMEM_DYN);

    float* g_At_p;  cudaGetSymbolAddress((void**)&g_At_p, g_At);
    float* g_Vt_p;  cudaGetSymbolAddress((void**)&g_Vt_p, g_Vt);

    dim3 ggrid(DD / 128, SS / 128, NB);  // (4, 16, 4)
    dim3 wgrid(SS / 128, SS / 128, NB);  // (16, 16, 4)

    round_kernel<<<2048, 256>>>(A, g_At_p, NB * SS * SS / 4);
    round_kernel<<<512, 256>>>(V, g_Vt_p, NB * SS * DD / 4);
    transpose_kernel<<<dim3(DD / 32, SS / 32, NB), 256>>>(V);
    rownorm_kernel<<<NB * SS, 128>>>(g_Vt_p, 0);
    gemm_tc<<<ggrid, NTHREADS, SMEM_DYN>>>(nullptr, M, 0, 0);
    for (int it = 0; it < 3; ++it) {
        float* g_Mt_p;  cudaGetSymbolAddress((void**)&g_Mt_p, g_Mt);
        rownorm_kernel<<<NB * SS, 128>>>(g_Mt_p, 1);
        wdist_tc<<<wgrid, NTHREADS, SMEM_DYN>>>(A);
        gemm_tc<<<ggrid, NTHREADS, SMEM_DYN>>>(nullptr, M, 1, 1);
    }
}

// round 10
// speedup vs baseline: 1.8723x; 1.1088x over previous
#include <cuda_runtime.h>
#include <math.h>
#include <stdint.h>

#define SS 2048
#define DD 512
#define NB 4
#define KC 32
#define NTHREADS 256                    // 8 warps, 2x4 grid, warp tile 64x32
#define LDSW 36                         // smem row stride in floats (conflict-free)
#define STAGE_U32 (2 * 128 * LDSW)      // X tile + Y tile per stage
#define STAGE_BYTES (STAGE_U32 * 4)     // 36864
#define NSTAGE 3
#define SMEM_DYN (NSTAGE * STAGE_BYTES) // 110592

// ---------------- scratch (allocation-free device globals) ----------------
__device__ float g_W[(size_t)NB * SS * SS];    // 64 MB rounded weight matrix
__device__ float g_At[(size_t)NB * SS * SS];   // 64 MB rounded A
__device__ float g_Vt[(size_t)NB * SS * DD];   // 16 MB rounded V
__device__ float g_VTt[(size_t)NB * DD * SS];  // 16 MB rounded V^T [n][k]
__device__ float g_Mt[(size_t)NB * SS * DD];   // 16 MB rounded M
__device__ float g_l1[NB * SS];
__device__ float g_m2[NB * SS];
__device__ float g_v2[NB * SS];

// ---------------- helpers ----------------
__device__ __forceinline__ float f2tf32f(float x) {
    uint32_t r;
    asm("cvt.rna.tf32.f32 %0, %1;" : "=r"(r) : "f"(x));
    return __uint_as_float(r);
}
__device__ __forceinline__ uint32_t smem_u32(const void* p) {
    uint32_t a;
    asm("{ .reg .u64 t; cvta.to.shared.u64 t, %1; cvt.u32.u64 %0, t; }"
        : "=r"(a) : "l"(p));
    return a;
}
__device__ __forceinline__ void cp16(uint32_t saddr, const void* gaddr) {
    asm volatile("cp.async.cg.shared.global [%0], [%1], 16;"
                 :: "r"(saddr), "l"(gaddr) : "memory");
}
__device__ __forceinline__ void cp_commit() {
    asm volatile("cp.async.commit_group;" ::: "memory");
}
template <int N>
__device__ __forceinline__ void cp_wait() {
    asm volatile("cp.async.wait_group %0;" :: "n"(N) : "memory");
}
__device__ __forceinline__ void ldsm4(uint32_t* r, uint32_t addr) {
    asm volatile("ldmatrix.sync.aligned.m8n8.x4.shared.b16 {%0,%1,%2,%3}, [%4];"
                 : "=r"(r[0]), "=r"(r[1]), "=r"(r[2]), "=r"(r[3]) : "r"(addr));
}
__device__ __forceinline__ void mma_tf32(float* c, const uint32_t* a, const uint32_t* b) {
    asm volatile(
        "mma.sync.aligned.m16n8k8.row.col.f32.tf32.tf32.f32 "
        "{%0,%1,%2,%3}, {%4,%5,%6,%7}, {%8,%9}, {%0,%1,%2,%3};"
        : "+f"(c[0]), "+f"(c[1]), "+f"(c[2]), "+f"(c[3])
        : "r"(a[0]), "r"(a[1]), "r"(a[2]), "r"(a[3]), "r"(b[0]), "r"(b[1]));
}

// ---------------------------------------------------------------------------
// Issue one stage: 128x32 X tile + 128x32 Y tile via cp.async (data already
// tf32-rounded in gmem). 8 x 16B per thread. Commits one group.
// ---------------------------------------------------------------------------
__device__ __forceinline__ void issue_stage(const float* __restrict__ X,
                                            const float* __restrict__ Y,
                                            int ldx, int ldy, int m0, int n0,
                                            int k0, uint32_t sbuf, int tid) {
#pragma unroll
    for (int p = 0; p < 4; ++p) {
        int idx = tid + p * NTHREADS;
        int row = idx >> 3, kq = (idx & 7) << 2;
        cp16(sbuf + (row * LDSW + kq) * 4,
             X + (size_t)(m0 + row) * ldx + k0 + kq);
    }
    uint32_t ybuf = sbuf + 128 * LDSW * 4;
#pragma unroll
    for (int p = 0; p < 4; ++p) {
        int idx = tid + p * NTHREADS;
        int row = idx >> 3, kq = (idx & 7) << 2;
        cp16(ybuf + (row * LDSW + kq) * 4,
             Y + (size_t)(n0 + row) * ldy + k0 + kq);
    }
    cp_commit();
}

// ---------------------------------------------------------------------------
// One KC=32 chunk via ldmatrix. Warp tile 64(m) x 32(n): 4 mf x 4 nf.
// aoff[mf], boff[p] are per-lane byte offsets (LDSM addressing).
// ---------------------------------------------------------------------------
__device__ __forceinline__ void compute_chunk(uint32_t sb, float acc[4][4][4],
                                              const uint32_t* aoff,
                                              const uint32_t* boff) {
    uint32_t ys = sb + 128 * LDSW * 4;
#pragma unroll
    for (int ks = 0; ks < 4; ++ks) {
        uint32_t kb = ks * 8 * 4;
        uint32_t af[4][4], bf[4][2];
#pragma unroll
        for (int mf = 0; mf < 4; ++mf) ldsm4(af[mf], sb + aoff[mf] + kb);
#pragma unroll
        for (int p = 0; p < 2; ++p) {
            uint32_t r[4];
            ldsm4(r, ys + boff[p] + kb);
            bf[2 * p][0] = r[0];
            bf[2 * p][1] = r[1];
            bf[2 * p + 1][0] = r[2];
            bf[2 * p + 1][1] = r[3];
        }
#pragma unroll
        for (int mf = 0; mf < 4; ++mf)
#pragma unroll
            for (int nf = 0; nf < 4; ++nf)
                mma_tf32(acc[mf][nf], af[mf], bf[nf]);
    }
}

// ---------------------------------------------------------------------------
// Multistage cp.async mainloop (prefetch depth 2, 3 buffers, 1 sync/chunk):
//   acc += X[m0:+128,:] @ Y[n0:+128,:]^T  over K = nch*KC.
// ---------------------------------------------------------------------------
__device__ __forceinline__ void mainloop(const float* X, const float* Y,
                                         int ldx, int ldy, int nch,
                                         int m0, int n0, uint32_t* dyn,
                                         float acc[4][4][4], int tid,
                                         const uint32_t* aoff,
                                         const uint32_t* boff) {
    uint32_t sb = smem_u32(dyn);
    issue_stage(X, Y, ldx, ldy, m0, n0, 0, sb, tid);
    issue_stage(X, Y, ldx, ldy, m0, n0, KC, sb + STAGE_BYTES, tid);
    for (int ch = 0; ch < nch; ++ch) {
        cp_wait<1>();
        __syncthreads();
        if (ch + 2 < nch)
            issue_stage(X, Y, ldx, ldy, m0, n0, (ch + 2) * KC,
                        sb + ((ch + 2) % NSTAGE) * STAGE_BYTES, tid);
        else
            cp_commit();  // keep wait_group accounting consistent in the tail
        compute_chunk(sb + (ch % NSTAGE) * STAGE_BYTES, acc, aoff, boff);
    }
}

// ---------------------------------------------------------------------------
// Elementwise rna-round to tf32 bits (grid-stride, float4).
// ---------------------------------------------------------------------------
__global__ void round_kernel(const float* __restrict__ in, float* __restrict__ out,
                             int n4) {
    int i = blockIdx.x * blockDim.x + threadIdx.x;
    int stride = gridDim.x * blockDim.x;
    for (; i < n4; i += stride) {
        float4 v = reinterpret_cast<const float4*>(in)[i];
        v.x = f2tf32f(v.x); v.y = f2tf32f(v.y); v.z = f2tf32f(v.z); v.w = f2tf32f(v.w);
        reinterpret_cast<float4*>(out)[i] = v;
    }
}

// ---------------------------------------------------------------------------
// Row squared-norms of rounded input; which=0 -> g_v2, which=1 -> g_m2+zero l1.
// ---------------------------------------------------------------------------
__global__ void rownorm_kernel(const float* __restrict__ X, int which) {
    int row = blockIdx.x;
    const float4* xp = reinterpret_cast<const float4*>(X + (size_t)row * DD);
    float4 v = xp[threadIdx.x];
    float s = v.x * v.x + v.y * v.y + v.z * v.z + v.w * v.w;
#pragma unroll
    for (int o = 16; o > 0; o >>= 1) s += __shfl_down_sync(0xffffffffu, s, o);
    __shared__ float ws[4];
    if ((threadIdx.x & 31) == 0) ws[threadIdx.x >> 5] = s;
    __syncthreads();
    if (threadIdx.x == 0) {
        float tot = ws[0] + ws[1] + ws[2] + ws[3];
        if (which) { g_m2[row] = tot; g_l1[row] = 0.0f; }
        else       { g_v2[row] = tot; }
    }
}

// ---------------------------------------------------------------------------
// g_VTt[b][n][k] = round(V[b][k][n])
// ---------------------------------------------------------------------------
__global__ void transpose_kernel(const float* __restrict__ V) {
    __shared__ float t[32][33];
    int b = blockIdx.z;
    const float* Vp = V + (size_t)b * SS * DD;
    float* Tp = g_VTt + (size_t)b * DD * SS;
    int x0 = blockIdx.x * 32;  // n
    int y0 = blockIdx.y * 32;  // k
    int tx = threadIdx.x & 31, ty = threadIdx.x >> 5;
#pragma unroll
    for (int i = ty; i < 32; i += 8)
        t[i][tx] = f2tf32f(Vp[(size_t)(y0 + i) * DD + x0 + tx]);
    __syncthreads();
#pragma unroll
    for (int i = ty; i < 32; i += 8)
        Tp[(size_t)(x0 + i) * SS + y0 + tx] = t[tx][i];
}

// ---------------------------------------------------------------------------
// GEMM: out[m,n] = scale(m) * sum_k X[m,k]*VTt[n,k]   (N = DD = 512)
// use_w: X = g_W else g_At. use_l1: scale = 1/max(l1,1e-12).
// final_out: write fp32 to C (harness output); else write rounded to g_Mt.
// ---------------------------------------------------------------------------
__global__ void __launch_bounds__(NTHREADS, 2)
gemm_tc(float* __restrict__ C, int use_w, int use_l1, int final_out) {
    extern __shared__ uint32_t dyn[];
    int tid = threadIdx.x;
    int wid = tid >> 5, lane = tid & 31;
    int wm = wid >> 2, wn = wid & 3;
    int g = lane >> 2, tg = lane & 3;
    int q = lane >> 3, lr = lane & 7;
    int b = blockIdx.z;
    int n0 = blockIdx.x * 128, m0 = blockIdx.y * 128;
    const float* X = (use_w ? g_W : g_At) + (size_t)b * SS * SS;
    const float* Y = g_VTt + (size_t)b * DD * SS;

    uint32_t aoff[4], boff[2];
#pragma unroll
    for (int mf = 0; mf < 4; ++mf)
        aoff[mf] = ((wm * 64 + mf * 16 + (q & 1) * 8 + lr) * LDSW + (q >> 1) * 4) * 4;
#pragma unroll
    for (int p = 0; p < 2; ++p)
        boff[p] = ((wn * 32 + p * 16 + (q >> 1) * 8 + lr) * LDSW + (q & 1) * 4) * 4;

    float acc[4][4][4];
#pragma unroll
    for (int i = 0; i < 4; ++i)
#pragma unroll
        for (int j = 0; j < 4; ++j)
#pragma unroll
            for (int e = 0; e < 4; ++e) acc[i][j][e] = 0.0f;

    mainloop(X, Y, SS, SS, SS / KC, m0, n0, dyn, acc, tid, aoff, boff);

    float* Co = (final_out ? C : g_Mt) + (size_t)b * SS * DD;
#pragma unroll
    for (int mf = 0; mf < 4; ++mf) {
        int r1 = m0 + wm * 64 + mf * 16 + g;
        int r2 = r1 + 8;
        float s1 = 1.0f, s2 = 1.0f;
        if (use_l1) {
            s1 = 1.0f / fmaxf(g_l1[b * SS + r1], 1e-12f);
            s2 = 1.0f / fmaxf(g_l1[b * SS + r2], 1e-12f);
        }
#pragma unroll
        for (int nf = 0; nf < 4; ++nf) {
            int col = n0 + wn * 32 + nf * 8 + 2 * tg;
            float m0v = acc[mf][nf][0] * s1, m1v = acc[mf][nf][1] * s1;
            float m2v = acc[mf][nf][2] * s2, m3v = acc[mf][nf][3] * s2;
            if (!final_out) {
                m0v = f2tf32f(m0v); m1v = f2tf32f(m1v);
                m2v = f2tf32f(m2v); m3v = f2tf32f(m3v);
            }
            *reinterpret_cast<float2*>(Co + (size_t)r1 * DD + col) = make_float2(m0v, m1v);
            *reinterpret_cast<float2*>(Co + (size_t)r2 * DD + col) = make_float2(m2v, m3v);
        }
    }
}

// ---------------------------------------------------------------------------
// W[i,j] = round(A[i,j]/(sqrt(max(m2[i]+v2[j]-2*Mt_i.Vt_j,0))+0.01)); l1 sums.
// ---------------------------------------------------------------------------
__global__ void __launch_bounds__(NTHREADS, 2)
wdist_tc(const float* __restrict__ A) {
    extern __shared__ uint32_t dyn[];
    int tid = threadIdx.x;
    int wid = tid >> 5, lane = tid & 31;
    int wm = wid >> 2, wn = wid & 3;
    int g = lane >> 2, tg = lane & 3;
    int q = lane >> 3, lr = lane & 7;
    int b = blockIdx.z;
    int j0 = blockIdx.x * 128, i0 = blockIdx.y * 128;
    const float* Mp = g_Mt + (size_t)b * SS * DD;
    const float* Vp = g_Vt + (size_t)b * SS * DD;
    const float* Ap = A + (size_t)b * SS * SS;
    float* Wp = g_W + (size_t)b * SS * SS;
    const float* v2p = g_v2 + b * SS;

    uint32_t aoff[4], boff[2];
#pragma unroll
    for (int mf = 0; mf < 4; ++mf)
        aoff[mf] = ((wm * 64 + mf * 16 + (q & 1) * 8 + lr) * LDSW + (q >> 1) * 4) * 4;
#pragma unroll
    for (int p = 0; p < 2; ++p)
        boff[p] = ((wn * 32 + p * 16 + (q >> 1) * 8 + lr) * LDSW + (q & 1) * 4) * 4;

    float acc[4][4][4];
#pragma unroll
    for (int i = 0; i < 4; ++i)
#pragma unroll
        for (int j = 0; j < 4; ++j)
#pragma unroll
            for (int e = 0; e < 4; ++e) acc[i][j][e] = 0.0f;

    mainloop(Mp, Vp, DD, DD, DD / KC, i0, j0, dyn, acc, tid, aoff, boff);

#pragma unroll
    for (int mf = 0; mf < 4; ++mf) {
        int r1 = i0 + wm * 64 + mf * 16 + g;
        int r2 = r1 + 8;
        float m21 = g_m2[b * SS + r1];
        float m22 = g_m2[b * SS + r2];
        float rs1 = 0.0f, rs2 = 0.0f;
#pragma unroll
        for (int nf = 0; nf < 4; ++nf) {
            int jj = j0 + wn * 32 + nf * 8 + 2 * tg;
            float v2a = v2p[jj], v2b = v2p[jj + 1];
            float2 a1 = *reinterpret_cast<const float2*>(Ap + (size_t)r1 * SS + jj);
            float2 a2 = *reinterpret_cast<const float2*>(Ap + (size_t)r2 * SS + jj);
            float d;
            d = sqrtf(fmaxf(m21 + v2a - 2.0f * acc[mf][nf][0], 0.0f));
            float w0 = f2tf32f(a1.x * __frcp_rn(d + 0.01f));
            d = sqrtf(fmaxf(m21 + v2b - 2.0f * acc[mf][nf][1], 0.0f));
            float w1 = f2tf32f(a1.y * __frcp_rn(d + 0.01f));
            d = sqrtf(fmaxf(m22 + v2a - 2.0f * acc[mf][nf][2], 0.0f));
            float w2 = f2tf32f(a2.x * __frcp_rn(d + 0.01f));
            d = sqrtf(fmaxf(m22 + v2b - 2.0f * acc[mf][nf][3], 0.0f));
            float w3 = f2tf32f(a2.y * __frcp_rn(d + 0.01f));
            rs1 += fabsf(w0) + fabsf(w1);
            rs2 += fabsf(w2) + fabsf(w3);
            *reinterpret_cast<float2*>(Wp + (size_t)r1 * SS + jj) = make_float2(w0, w1);
            *reinterpret_cast<float2*>(Wp + (size_t)r2 * SS + jj) = make_float2(w2, w3);
        }
        rs1 += __shfl_xor_sync(0xffffffffu, rs1, 1);
        rs1 += __shfl_xor_sync(0xffffffffu, rs1, 2);
        rs2 += __shfl_xor_sync(0xffffffffu, rs2, 1);
        rs2 += __shfl_xor_sync(0xffffffffu, rs2, 2);
        if (tg == 0) {
            atomicAdd(&g_l1[b * SS + r1], rs1);
            atomicAdd(&g_l1[b * SS + r2], rs2);
        }
    }
}

// ---------------------------------------------------------------------------
extern "C" void kernel_launch(void* const* d_in, const int* in_sizes, int n_in,
                              void* d_out, int out_size) {
    const float* A = (const float*)d_in[0];  // (4, 2048, 2048)
    const float* V = (const float*)d_in[1];  // (4, 2048, 512)
    float* M = (float*)d_out;                // (4, 2048, 512)

    cudaFuncSetAttribute(gemm_tc, cudaFuncAttributeMaxDynamicSharedMemorySize, SMEM_DYN);
    cudaFuncSetAttribute(wdist_tc, cudaFuncAttributeMaxDynamicSharedMemorySize, SMEM_DYN);

    float* g_At_p;  cudaGetSymbolAddress((void**)&g_At_p, g_At);
    float* g_Vt_p;  cudaGetSymbolAddress((void**)&g_Vt_p, g_Vt);
    float* g_Mt_p;  cudaGetSymbolAddress((void**)&g_Mt_p, g_Mt);

    dim3 ggrid(DD / 128, SS / 128, NB);  // (4, 16, 4)
    dim3 wgrid(SS / 128, SS / 128, NB);  // (16, 16, 4)

    round_kernel<<<2048, 256>>>(A, g_At_p, NB * SS * SS / 4);
    round_kernel<<<512, 256>>>(V, g_Vt_p, NB * SS * DD / 4);
    transpose_kernel<<<dim3(DD / 32, SS / 32, NB), 256>>>(V);
    rownorm_kernel<<<NB * SS, 128>>>(g_Vt_p, 0);
    gemm_tc<<<ggrid, NTHREADS, SMEM_DYN>>>(M, 0, 0, 0);
    for (int it = 0; it < 3; ++it) {
        rownorm_kernel<<<NB * SS, 128>>>(g_Mt_p, 1);
        wdist_tc<<<wgrid, NTHREADS, SMEM_DYN>>>(A);
        gemm_tc<<<ggrid, NTHREADS, SMEM_DYN>>>(M, 1, 1, it == 2);
    }
}

// round 11
// speedup vs baseline: 2.7710x; 1.4800x over previous
#include <cuda_runtime.h>
#include <cuda_fp16.h>
#include <math.h>
#include <stdint.h>

#define SS 2048
#define DD 512
#define NB 4
#define KC 32
#define NTHREADS 256                    // 8 warps, 2x4 grid, warp tile 64x32
#define LDSH 40                         // smem row stride in halves (80 B)
#define XTILE_BYTES (128 * LDSH * 2)    // 10240
#define STAGE_BYTES (2 * XTILE_BYTES)   // 20480
#define NSTAGE 4
#define SMEM_DYN (NSTAGE * STAGE_BYTES) // 81920

// ---------------- scratch (allocation-free device globals, fp16) ----------
__device__ __half g_W[(size_t)NB * SS * SS];    // 32 MB weight matrix
__device__ __half g_Ah[(size_t)NB * SS * SS];   // 32 MB rounded A
__device__ __half g_Vh[(size_t)NB * SS * DD];   // 8 MB rounded V
__device__ __half g_VTh[(size_t)NB * DD * SS];  // 8 MB rounded V^T [n][k]
__device__ __half g_Mh[(size_t)NB * SS * DD];   // 8 MB rounded M
__device__ float g_l1[NB * SS];
__device__ float g_m2[NB * SS];
__device__ float g_v2[NB * SS];

// ---------------- helpers ----------------
__device__ __forceinline__ uint32_t smem_u32(const void* p) {
    uint32_t a;
    asm("{ .reg .u64 t; cvta.to.shared.u64 t, %1; cvt.u32.u64 %0, t; }"
        : "=r"(a) : "l"(p));
    return a;
}
__device__ __forceinline__ void cp16(uint32_t saddr, const void* gaddr) {
    asm volatile("cp.async.cg.shared.global [%0], [%1], 16;"
                 :: "r"(saddr), "l"(gaddr) : "memory");
}
__device__ __forceinline__ void cp_commit() {
    asm volatile("cp.async.commit_group;" ::: "memory");
}
template <int N>
__device__ __forceinline__ void cp_wait() {
    asm volatile("cp.async.wait_group %0;" :: "n"(N) : "memory");
}
__device__ __forceinline__ void ldsm4(uint32_t* r, uint32_t addr) {
    asm volatile("ldmatrix.sync.aligned.m8n8.x4.shared.b16 {%0,%1,%2,%3}, [%4];"
                 : "=r"(r[0]), "=r"(r[1]), "=r"(r[2]), "=r"(r[3]) : "r"(addr));
}
__device__ __forceinline__ void mma_f16(float* c, const uint32_t* a, const uint32_t* b) {
    asm volatile(
        "mma.sync.aligned.m16n8k16.row.col.f32.f16.f16.f32 "
        "{%0,%1,%2,%3}, {%4,%5,%6,%7}, {%8,%9}, {%0,%1,%2,%3};"
        : "+f"(c[0]), "+f"(c[1]), "+f"(c[2]), "+f"(c[3])
        : "r"(a[0]), "r"(a[1]), "r"(a[2]), "r"(a[3]), "r"(b[0]), "r"(b[1]));
}

// ---------------------------------------------------------------------------
// Issue one stage: 128x32 fp16 X tile + Y tile via cp.async. 4x16B per thread.
// ---------------------------------------------------------------------------
__device__ __forceinline__ void issue_stage(const __half* __restrict__ X,
                                            const __half* __restrict__ Y,
                                            int ldx, int ldy, int m0, int n0,
                                            int k0, uint32_t sbuf, int tid) {
#pragma unroll
    for (int p = 0; p < 2; ++p) {
        int idx = tid + p * NTHREADS;
        int row = idx >> 2, q = idx & 3;
        cp16(sbuf + (row * LDSH + q * 8) * 2,
             X + (size_t)(m0 + row) * ldx + k0 + q * 8);
    }
    uint32_t ybuf = sbuf + XTILE_BYTES;
#pragma unroll
    for (int p = 0; p < 2; ++p) {
        int idx = tid + p * NTHREADS;
        int row = idx >> 2, q = idx & 3;
        cp16(ybuf + (row * LDSH + q * 8) * 2,
             Y + (size_t)(n0 + row) * ldy + k0 + q * 8);
    }
    cp_commit();
}

// ---------------------------------------------------------------------------
// One KC=32 chunk: 2 k16 slices. Warp tile 64x32: 4 mf x 4 nf.
// Per slice: 4 ldsm.x4 (A) + 2 ldsm.x4 (B) + 16 MMA.
// ---------------------------------------------------------------------------
__device__ __forceinline__ void compute_chunk(uint32_t sb, float acc[4][4][4],
                                              const uint32_t* aoff,
                                              const uint32_t* boff) {
    uint32_t ys = sb + XTILE_BYTES;
#pragma unroll
    for (int ks = 0; ks < 2; ++ks) {
        uint32_t kb = ks * 16 * 2;  // 16 halves
        uint32_t af[4][4], bf[4][2];
#pragma unroll
        for (int mf = 0; mf < 4; ++mf) ldsm4(af[mf], sb + aoff[mf] + kb);
#pragma unroll
        for (int p = 0; p < 2; ++p) {
            uint32_t r[4];
            ldsm4(r, ys + boff[p] + kb);
            bf[2 * p][0] = r[0];
            bf[2 * p][1] = r[1];
            bf[2 * p + 1][0] = r[2];
            bf[2 * p + 1][1] = r[3];
        }
#pragma unroll
        for (int mf = 0; mf < 4; ++mf)
#pragma unroll
            for (int nf = 0; nf < 4; ++nf)
                mma_f16(acc[mf][nf], af[mf], bf[nf]);
    }
}

// ---------------------------------------------------------------------------
// 4-buffer cp.async mainloop (prefetch depth 3, 1 sync/chunk):
//   acc += X[m0:+128,:] @ Y[n0:+128,:]^T  over K = nch*KC.  (nch >= 3)
// ---------------------------------------------------------------------------
__device__ __forceinline__ void mainloop(const __half* X, const __half* Y,
                                         int ldx, int ldy, int nch,
                                         int m0, int n0, uint32_t* dyn,
                                         float acc[4][4][4], int tid,
                                         const uint32_t* aoff,
                                         const uint32_t* boff) {
    uint32_t sb = smem_u32(dyn);
    issue_stage(X, Y, ldx, ldy, m0, n0, 0, sb, tid);
    issue_stage(X, Y, ldx, ldy, m0, n0, KC, sb + STAGE_BYTES, tid);
    issue_stage(X, Y, ldx, ldy, m0, n0, 2 * KC, sb + 2 * STAGE_BYTES, tid);
    for (int ch = 0; ch < nch; ++ch) {
        cp_wait<2>();
        __syncthreads();
        if (ch + 3 < nch)
            issue_stage(X, Y, ldx, ldy, m0, n0, (ch + 3) * KC,
                        sb + ((ch + 3) & 3) * STAGE_BYTES, tid);
        else
            cp_commit();  // keep wait_group accounting consistent in the tail
        compute_chunk(sb + (ch & 3) * STAGE_BYTES, acc, aoff, boff);
    }
}

// ---------------------------------------------------------------------------
// Elementwise round fp32 -> fp16 (grid-stride, float4 in, half2x2 out).
// ---------------------------------------------------------------------------
__global__ void round_kernel(const float* __restrict__ in, __half* __restrict__ out,
                             int n4) {
    int i = blockIdx.x * blockDim.x + threadIdx.x;
    int stride = gridDim.x * blockDim.x;
    for (; i < n4; i += stride) {
        float4 v = reinterpret_cast<const float4*>(in)[i];
        __half2* o = reinterpret_cast<__half2*>(out) + 2 * i;
        o[0] = __floats2half2_rn(v.x, v.y);
        o[1] = __floats2half2_rn(v.z, v.w);
    }
}

// ---------------------------------------------------------------------------
// Row squared-norms of an fp16 (rows x DD) matrix.
// which=0 -> g_v2, which=1 -> g_m2 + zero g_l1.
// ---------------------------------------------------------------------------
__global__ void rownorm_kernel(const __half* __restrict__ X, int which) {
    int row = blockIdx.x;
    const __half2* xp = reinterpret_cast<const __half2*>(X + (size_t)row * DD);
    float s = 0.0f;
#pragma unroll
    for (int p = 0; p < 2; ++p) {
        float2 v = __half22float2(xp[threadIdx.x * 2 + p]);
        s += v.x * v.x + v.y * v.y;
    }
#pragma unroll
    for (int o = 16; o > 0; o >>= 1) s += __shfl_down_sync(0xffffffffu, s, o);
    __shared__ float ws[4];
    if ((threadIdx.x & 31) == 0) ws[threadIdx.x >> 5] = s;
    __syncthreads();
    if (threadIdx.x == 0) {
        float tot = ws[0] + ws[1] + ws[2] + ws[3];
        if (which) { g_m2[row] = tot; g_l1[row] = 0.0f; }
        else       { g_v2[row] = tot; }
    }
}

// ---------------------------------------------------------------------------
// g_VTh[b][n][k] = fp16(V[b][k][n])
// ---------------------------------------------------------------------------
__global__ void transpose_kernel(const float* __restrict__ V) {
    __shared__ float t[32][33];
    int b = blockIdx.z;
    const float* Vp = V + (size_t)b * SS * DD;
    __half* Tp = g_VTh + (size_t)b * DD * SS;
    int x0 = blockIdx.x * 32;  // n
    int y0 = blockIdx.y * 32;  // k
    int tx = threadIdx.x & 31, ty = threadIdx.x >> 5;
#pragma unroll
    for (int i = ty; i < 32; i += 8)
        t[i][tx] = Vp[(size_t)(y0 + i) * DD + x0 + tx];
    __syncthreads();
#pragma unroll
    for (int i = ty; i < 32; i += 8)
        Tp[(size_t)(x0 + i) * SS + y0 + tx] = __float2half_rn(t[tx][i]);
}

// ---------------------------------------------------------------------------
// GEMM: out[m,n] = scale(m) * sum_k X[m,k]*VTh[n,k]   (N = DD = 512)
// use_w: X = g_W else g_Ah. use_l1: scale = 1/max(l1,1e-12).
// final_out: write fp32 to C (harness output); else write fp16 to g_Mh.
// ---------------------------------------------------------------------------
__global__ void __launch_bounds__(NTHREADS, 2)
gemm_tc(float* __restrict__ C, int use_w, int use_l1, int final_out) {
    extern __shared__ uint32_t dyn[];
    int tid = threadIdx.x;
    int wid = tid >> 5, lane = tid & 31;
    int wm = wid >> 2, wn = wid & 3;
    int g = lane >> 2, tg = lane & 3;
    int q = lane >> 3, lr = lane & 7;
    int b = blockIdx.z;
    int n0 = blockIdx.x * 128, m0 = blockIdx.y * 128;
    const __half* X = (use_w ? g_W : g_Ah) + (size_t)b * SS * SS;
    const __half* Y = g_VTh + (size_t)b * DD * SS;

    uint32_t aoff[4], boff[2];
#pragma unroll
    for (int mf = 0; mf < 4; ++mf)
        aoff[mf] = ((wm * 64 + mf * 16 + (q & 1) * 8 + lr) * LDSH + (q >> 1) * 8) * 2;
#pragma unroll
    for (int p = 0; p < 2; ++p)
        boff[p] = ((wn * 32 + p * 16 + (q >> 1) * 8 + lr) * LDSH + (q & 1) * 8) * 2;

    float acc[4][4][4];
#pragma unroll
    for (int i = 0; i < 4; ++i)
#pragma unroll
        for (int j = 0; j < 4; ++j)
#pragma unroll
            for (int e = 0; e < 4; ++e) acc[i][j][e] = 0.0f;

    mainloop(X, Y, SS, SS, SS / KC, m0, n0, dyn, acc, tid, aoff, boff);

#pragma unroll
    for (int mf = 0; mf < 4; ++mf) {
        int r1 = m0 + wm * 64 + mf * 16 + g;
        int r2 = r1 + 8;
        float s1 = 1.0f, s2 = 1.0f;
        if (use_l1) {
            s1 = 1.0f / fmaxf(g_l1[b * SS + r1], 1e-12f);
            s2 = 1.0f / fmaxf(g_l1[b * SS + r2], 1e-12f);
        }
        if (final_out) {
            float* Co = C + (size_t)b * SS * DD;
#pragma unroll
            for (int nf = 0; nf < 4; ++nf) {
                int col = n0 + wn * 32 + nf * 8 + 2 * tg;
                *reinterpret_cast<float2*>(Co + (size_t)r1 * DD + col) =
                    make_float2(acc[mf][nf][0] * s1, acc[mf][nf][1] * s1);
                *reinterpret_cast<float2*>(Co + (size_t)r2 * DD + col) =
                    make_float2(acc[mf][nf][2] * s2, acc[mf][nf][3] * s2);
            }
        } else {
            __half* Mo = g_Mh + (size_t)b * SS * DD;
#pragma unroll
            for (int nf = 0; nf < 4; ++nf) {
                int col = n0 + wn * 32 + nf * 8 + 2 * tg;
                *reinterpret_cast<__half2*>(Mo + (size_t)r1 * DD + col) =
                    __floats2half2_rn(acc[mf][nf][0] * s1, acc[mf][nf][1] * s1);
                *reinterpret_cast<__half2*>(Mo + (size_t)r2 * DD + col) =
                    __floats2half2_rn(acc[mf][nf][2] * s2, acc[mf][nf][3] * s2);
            }
        }
    }
}

// ---------------------------------------------------------------------------
// W[i,j] = fp16(Ah[i,j] / (sqrt(max(m2[i]+v2[j]-2*Mh_i.Vh_j,0))+0.01)); l1 sums
// of the rounded values (consistent with the GEMM that consumes W).
// ---------------------------------------------------------------------------
__global__ void __launch_bounds__(NTHREADS, 2)
wdist_tc() {
    extern __shared__ uint32_t dyn[];
    int tid = threadIdx.x;
    int wid = tid >> 5, lane = tid & 31;
    int wm = wid >> 2, wn = wid & 3;
    int g = lane >> 2, tg = lane & 3;
    int q = lane >> 3, lr = lane & 7;
    int b = blockIdx.z;
    int j0 = blockIdx.x * 128, i0 = blockIdx.y * 128;
    const __half* Mp = g_Mh + (size_t)b * SS * DD;
    const __half* Vp = g_Vh + (size_t)b * SS * DD;
    const __half* Ap = g_Ah + (size_t)b * SS * SS;
    __half* Wp = g_W + (size_t)b * SS * SS;
    const float* v2p = g_v2 + b * SS;

    uint32_t aoff[4], boff[2];
#pragma unroll
    for (int mf = 0; mf < 4; ++mf)
        aoff[mf] = ((wm * 64 + mf * 16 + (q & 1) * 8 + lr) * LDSH + (q >> 1) * 8) * 2;
#pragma unroll
    for (int p = 0; p < 2; ++p)
        boff[p] = ((wn * 32 + p * 16 + (q >> 1) * 8 + lr) * LDSH + (q & 1) * 8) * 2;

    float acc[4][4][4];
#pragma unroll
    for (int i = 0; i < 4; ++i)
#pragma unroll
        for (int j = 0; j < 4; ++j)
#pragma unroll
            for (int e = 0; e < 4; ++e) acc[i][j][e] = 0.0f;

    mainloop(Mp, Vp, DD, DD, DD / KC, i0, j0, dyn, acc, tid, aoff, boff);

#pragma unroll
    for (int mf = 0; mf < 4; ++mf) {
        int r1 = i0 + wm * 64 + mf * 16 + g;
        int r2 = r1 + 8;
        float m21 = g_m2[b * SS + r1];
        float m22 = g_m2[b * SS + r2];
        float rs1 = 0.0f, rs2 = 0.0f;
#pragma unroll
        for (int nf = 0; nf < 4; ++nf) {
            int jj = j0 + wn * 32 + nf * 8 + 2 * tg;
            float v2a = v2p[jj], v2b = v2p[jj + 1];
            float2 a1 = __half22float2(
                *reinterpret_cast<const __half2*>(Ap + (size_t)r1 * SS + jj));
            float2 a2 = __half22float2(
                *reinterpret_cast<const __half2*>(Ap + (size_t)r2 * SS + jj));
            float d;
            d = sqrtf(fmaxf(m21 + v2a - 2.0f * acc[mf][nf][0], 0.0f));
            float w0 = a1.x * __frcp_rn(d + 0.01f);
            d = sqrtf(fmaxf(m21 + v2b - 2.0f * acc[mf][nf][1], 0.0f));
            float w1 = a1.y * __frcp_rn(d + 0.01f);
            d = sqrtf(fmaxf(m22 + v2a - 2.0f * acc[mf][nf][2], 0.0f));
            float w2 = a2.x * __frcp_rn(d + 0.01f);
            d = sqrtf(fmaxf(m22 + v2b - 2.0f * acc[mf][nf][3], 0.0f));
            float w3 = a2.y * __frcp_rn(d + 0.01f);
            __half2 h1 = __floats2half2_rn(w0, w1);
            __half2 h2 = __floats2half2_rn(w2, w3);
            float2 f1 = __half22float2(h1), f2 = __half22float2(h2);
            rs1 += fabsf(f1.x) + fabsf(f1.y);
            rs2 += fabsf(f2.x) + fabsf(f2.y);
            *reinterpret_cast<__half2*>(Wp + (size_t)r1 * SS + jj) = h1;
            *reinterpret_cast<__half2*>(Wp + (size_t)r2 * SS + jj) = h2;
        }
        rs1 += __shfl_xor_sync(0xffffffffu, rs1, 1);
        rs1 += __shfl_xor_sync(0xffffffffu, rs1, 2);
        rs2 += __shfl_xor_sync(0xffffffffu, rs2, 1);
        rs2 += __shfl_xor_sync(0xffffffffu, rs2, 2);
        if (tg == 0) {
            atomicAdd(&g_l1[b * SS + r1], rs1);
            atomicAdd(&g_l1[b * SS + r2], rs2);
        }
    }
}

// ---------------------------------------------------------------------------
extern "C" void kernel_launch(void* const* d_in, const int* in_sizes, int n_in,
                              void* d_out, int out_size) {
    const float* A = (const float*)d_in[0];  // (4, 2048, 2048)
    const float* V = (const float*)d_in[1];  // (4, 2048, 512)
    float* M = (float*)d_out;                // (4, 2048, 512)

    cudaFuncSetAttribute(gemm_tc, cudaFuncAttributeMaxDynamicSharedMemorySize, SMEM_DYN);
    cudaFuncSetAttribute(wdist_tc, cudaFuncAttributeMaxDynamicSharedMemorySize, SMEM_DYN);

    __half* g_Ah_p;  cudaGetSymbolAddress((void**)&g_Ah_p, g_Ah);
    __half* g_Vh_p;  cudaGetSymbolAddress((void**)&g_Vh_p, g_Vh);
    __half* g_Mh_p;  cudaGetSymbolAddress((void**)&g_Mh_p, g_Mh);

    dim3 ggrid(DD / 128, SS / 128, NB);  // (4, 16, 4)
    dim3 wgrid(SS / 128, SS / 128, NB);  // (16, 16, 4)

    round_kernel<<<2048, 256>>>(A, g_Ah_p, NB * SS * SS / 4);
    round_kernel<<<512, 256>>>(V, g_Vh_p, NB * SS * DD / 4);
    transpose_kernel<<<dim3(DD / 32, SS / 32, NB), 256>>>(V);
    rownorm_kernel<<<NB * SS, 128>>>(g_Vh_p, 0);
    gemm_tc<<<ggrid, NTHREADS, SMEM_DYN>>>(M, 0, 0, 0);
    for (int it = 0; it < 3; ++it) {
        rownorm_kernel<<<NB * SS, 128>>>(g_Mh_p, 1);
        wdist_tc<<<wgrid, NTHREADS, SMEM_DYN>>>();
        gemm_tc<<<ggrid, NTHREADS, SMEM_DYN>>>(M, 1, 1, it == 2);
    }
}

// round 12
// speedup vs baseline: 2.7797x; 1.0031x over previous
#include <cuda_runtime.h>
#include <cuda_fp16.h>
#include <math.h>
#include <stdint.h>

#define SS 2048
#define DD 512
#define NB 4
#define KC 32
#define NTHREADS 256                    // 8 warps, 2x4 grid, warp tile 64x32
#define LDSH 40                         // smem row stride in halves (80 B)
#define XTILE_BYTES (128 * LDSH * 2)    // 10240
#define STAGE_BYTES (2 * XTILE_BYTES)   // 20480
#define NSTAGE 4
#define SMEM_PIPE (NSTAGE * STAGE_BYTES) // 81920
#define SMEM_DYN (SMEM_PIPE + 512)       // + reduction buffer

// ---------------- scratch (allocation-free device globals, fp16) ----------
__device__ __half g_W[(size_t)NB * SS * SS];    // 32 MB weight matrix
__device__ __half g_Ah[(size_t)NB * SS * SS];   // 32 MB rounded A
__device__ __half g_Vh[(size_t)NB * SS * DD];   // 8 MB rounded V
__device__ __half g_VTh[(size_t)NB * DD * SS];  // 8 MB rounded V^T [n][k]
__device__ __half g_Mh[(size_t)NB * SS * DD];   // 8 MB rounded M
__device__ float g_v2[NB * SS];
__device__ float g_m2part[4][NB * SS];          // per-n0-block partial |M|^2
__device__ float g_l1part[16][NB * SS];         // per-j-block partial l1 sums

// ---------------- helpers ----------------
__device__ __forceinline__ uint32_t smem_u32(const void* p) {
    uint32_t a;
    asm("{ .reg .u64 t; cvta.to.shared.u64 t, %1; cvt.u32.u64 %0, t; }"
        : "=r"(a) : "l"(p));
    return a;
}
__device__ __forceinline__ void cp16(uint32_t saddr, const void* gaddr) {
    asm volatile("cp.async.cg.shared.global [%0], [%1], 16;"
                 :: "r"(saddr), "l"(gaddr) : "memory");
}
__device__ __forceinline__ void cp_commit() {
    asm volatile("cp.async.commit_group;" ::: "memory");
}
template <int N>
__device__ __forceinline__ void cp_wait() {
    asm volatile("cp.async.wait_group %0;" :: "n"(N) : "memory");
}
__device__ __forceinline__ void ldsm4(uint32_t* r, uint32_t addr) {
    asm volatile("ldmatrix.sync.aligned.m8n8.x4.shared.b16 {%0,%1,%2,%3}, [%4];"
                 : "=r"(r[0]), "=r"(r[1]), "=r"(r[2]), "=r"(r[3]) : "r"(addr));
}
__device__ __forceinline__ void mma_f16(float* c, const uint32_t* a, const uint32_t* b) {
    asm volatile(
        "mma.sync.aligned.m16n8k16.row.col.f32.f16.f16.f32 "
        "{%0,%1,%2,%3}, {%4,%5,%6,%7}, {%8,%9}, {%0,%1,%2,%3};"
        : "+f"(c[0]), "+f"(c[1]), "+f"(c[2]), "+f"(c[3])
        : "r"(a[0]), "r"(a[1]), "r"(a[2]), "r"(a[3]), "r"(b[0]), "r"(b[1]));
}

// ---------------------------------------------------------------------------
// Issue one stage: 128x32 fp16 X tile + Y tile via cp.async. 4x16B per thread.
// ---------------------------------------------------------------------------
__device__ __forceinline__ void issue_stage(const __half* __restrict__ X,
                                            const __half* __restrict__ Y,
                                            int ldx, int ldy, int m0, int n0,
                                            int k0, uint32_t sbuf, int tid) {
#pragma unroll
    for (int p = 0; p < 2; ++p) {
        int idx = tid + p * NTHREADS;
        int row = idx >> 2, q = idx & 3;
        cp16(sbuf + (row * LDSH + q * 8) * 2,
             X + (size_t)(m0 + row) * ldx + k0 + q * 8);
    }
    uint32_t ybuf = sbuf + XTILE_BYTES;
#pragma unroll
    for (int p = 0; p < 2; ++p) {
        int idx = tid + p * NTHREADS;
        int row = idx >> 2, q = idx & 3;
        cp16(ybuf + (row * LDSH + q * 8) * 2,
             Y + (size_t)(n0 + row) * ldy + k0 + q * 8);
    }
    cp_commit();
}

// ---------------------------------------------------------------------------
// One KC=32 chunk: 2 k16 slices. Warp tile 64x32: 4 mf x 4 nf.
// ---------------------------------------------------------------------------
__device__ __forceinline__ void compute_chunk(uint32_t sb, float acc[4][4][4],
                                              const uint32_t* aoff,
                                              const uint32_t* boff) {
    uint32_t ys = sb + XTILE_BYTES;
#pragma unroll
    for (int ks = 0; ks < 2; ++ks) {
        uint32_t kb = ks * 16 * 2;
        uint32_t af[4][4], bf[4][2];
#pragma unroll
        for (int mf = 0; mf < 4; ++mf) ldsm4(af[mf], sb + aoff[mf] + kb);
#pragma unroll
        for (int p = 0; p < 2; ++p) {
            uint32_t r[4];
            ldsm4(r, ys + boff[p] + kb);
            bf[2 * p][0] = r[0];
            bf[2 * p][1] = r[1];
            bf[2 * p + 1][0] = r[2];
            bf[2 * p + 1][1] = r[3];
        }
#pragma unroll
        for (int mf = 0; mf < 4; ++mf)
#pragma unroll
            for (int nf = 0; nf < 4; ++nf)
                mma_f16(acc[mf][nf], af[mf], bf[nf]);
    }
}

// ---------------------------------------------------------------------------
// 4-buffer cp.async mainloop (prefetch depth 3, 1 sync/chunk).
// ---------------------------------------------------------------------------
__device__ __forceinline__ void mainloop(const __half* X, const __half* Y,
                                         int ldx, int ldy, int nch,
                                         int m0, int n0, uint32_t* dyn,
                                         float acc[4][4][4], int tid,
                                         const uint32_t* aoff,
                                         const uint32_t* boff) {
    uint32_t sb = smem_u32(dyn);
    issue_stage(X, Y, ldx, ldy, m0, n0, 0, sb, tid);
    issue_stage(X, Y, ldx, ldy, m0, n0, KC, sb + STAGE_BYTES, tid);
    issue_stage(X, Y, ldx, ldy, m0, n0, 2 * KC, sb + 2 * STAGE_BYTES, tid);
    for (int ch = 0; ch < nch; ++ch) {
        cp_wait<2>();
        __syncthreads();
        if (ch + 3 < nch)
            issue_stage(X, Y, ldx, ldy, m0, n0, (ch + 3) * KC,
                        sb + ((ch + 3) & 3) * STAGE_BYTES, tid);
        else
            cp_commit();
        compute_chunk(sb + (ch & 3) * STAGE_BYTES, acc, aoff, boff);
    }
}

// ---------------------------------------------------------------------------
// Elementwise round fp32 -> fp16 (grid-stride, float4 in).
// ---------------------------------------------------------------------------
__global__ void round_kernel(const float* __restrict__ in, __half* __restrict__ out,
                             int n4) {
    int i = blockIdx.x * blockDim.x + threadIdx.x;
    int stride = gridDim.x * blockDim.x;
    for (; i < n4; i += stride) {
        float4 v = reinterpret_cast<const float4*>(in)[i];
        __half2* o = reinterpret_cast<__half2*>(out) + 2 * i;
        o[0] = __floats2half2_rn(v.x, v.y);
        o[1] = __floats2half2_rn(v.z, v.w);
    }
}

// ---------------------------------------------------------------------------
// Row squared-norms of fp16 V -> g_v2.
// ---------------------------------------------------------------------------
__global__ void rownorm_kernel(const __half* __restrict__ X) {
    int row = blockIdx.x;
    const __half2* xp = reinterpret_cast<const __half2*>(X + (size_t)row * DD);
    float s = 0.0f;
#pragma unroll
    for (int p = 0; p < 2; ++p) {
        float2 v = __half22float2(xp[threadIdx.x * 2 + p]);
        s += v.x * v.x + v.y * v.y;
    }
#pragma unroll
    for (int o = 16; o > 0; o >>= 1) s += __shfl_down_sync(0xffffffffu, s, o);
    __shared__ float ws[4];
    if ((threadIdx.x & 31) == 0) ws[threadIdx.x >> 5] = s;
    __syncthreads();
    if (threadIdx.x == 0) g_v2[row] = ws[0] + ws[1] + ws[2] + ws[3];
}

// ---------------------------------------------------------------------------
// g_VTh[b][n][k] = fp16(V[b][k][n])
// ---------------------------------------------------------------------------
__global__ void transpose_kernel(const float* __restrict__ V) {
    __shared__ float t[32][33];
    int b = blockIdx.z;
    const float* Vp = V + (size_t)b * SS * DD;
    __half* Tp = g_VTh + (size_t)b * DD * SS;
    int x0 = blockIdx.x * 32;
    int y0 = blockIdx.y * 32;
    int tx = threadIdx.x & 31, ty = threadIdx.x >> 5;
#pragma unroll
    for (int i = ty; i < 32; i += 8)
        t[i][tx] = Vp[(size_t)(y0 + i) * DD + x0 + tx];
    __syncthreads();
#pragma unroll
    for (int i = ty; i < 32; i += 8)
        Tp[(size_t)(x0 + i) * SS + y0 + tx] = __float2half_rn(t[tx][i]);
}

// ---------------------------------------------------------------------------
// GEMM: out[m,n] = scale(m) * sum_k X[m,k]*VTh[n,k]   (N = DD = 512)
// use_w: X = g_W else g_Ah. use_l1: scale = 1/max(sum l1part,1e-12).
// final_out: write fp32 C; else write fp16 g_Mh + m2part[n0blk].
// ---------------------------------------------------------------------------
__global__ void __launch_bounds__(NTHREADS, 2)
gemm_tc(float* __restrict__ C, int use_w, int use_l1, int final_out) {
    extern __shared__ uint32_t dyn[];
    float* s_red = (float*)((char*)dyn + SMEM_PIPE);
    int tid = threadIdx.x;
    int wid = tid >> 5, lane = tid & 31;
    int wm = wid >> 2, wn = wid & 3;
    int g = lane >> 2, tg = lane & 3;
    int q = lane >> 3, lr = lane & 7;
    int b = blockIdx.z;
    int n0 = blockIdx.x * 128, m0 = blockIdx.y * 128;
    const __half* X = (use_w ? g_W : g_Ah) + (size_t)b * SS * SS;
    const __half* Y = g_VTh + (size_t)b * DD * SS;

    uint32_t aoff[4], boff[2];
#pragma unroll
    for (int mf = 0; mf < 4; ++mf)
        aoff[mf] = ((wm * 64 + mf * 16 + (q & 1) * 8 + lr) * LDSH + (q >> 1) * 8) * 2;
#pragma unroll
    for (int p = 0; p < 2; ++p)
        boff[p] = ((wn * 32 + p * 16 + (q >> 1) * 8 + lr) * LDSH + (q & 1) * 8) * 2;

    float acc[4][4][4];
#pragma unroll
    for (int i = 0; i < 4; ++i)
#pragma unroll
        for (int j = 0; j < 4; ++j)
#pragma unroll
            for (int e = 0; e < 4; ++e) acc[i][j][e] = 0.0f;

    mainloop(X, Y, SS, SS, SS / KC, m0, n0, dyn, acc, tid, aoff, boff);

    // cooperative l1 gather: s_red[r] = sum over 16 j-block partials
    float s1v[4], s2v[4];
    if (use_l1) {
        if (tid < 128) {
            float s = 0.0f;
#pragma unroll
            for (int p = 0; p < 16; ++p) s += g_l1part[p][b * SS + m0 + tid];
            s_red[tid] = s;
        }
        __syncthreads();
#pragma unroll
        for (int mf = 0; mf < 4; ++mf) {
            int rr = wm * 64 + mf * 16 + g;
            s1v[mf] = 1.0f / fmaxf(s_red[rr], 1e-12f);
            s2v[mf] = 1.0f / fmaxf(s_red[rr + 8], 1e-12f);
        }
        __syncthreads();
    } else {
#pragma unroll
        for (int mf = 0; mf < 4; ++mf) { s1v[mf] = 1.0f; s2v[mf] = 1.0f; }
    }

    if (final_out) {
        float* Co = C + (size_t)b * SS * DD;
#pragma unroll
        for (int mf = 0; mf < 4; ++mf) {
            int r1 = m0 + wm * 64 + mf * 16 + g;
            int r2 = r1 + 8;
#pragma unroll
            for (int nf = 0; nf < 4; ++nf) {
                int col = n0 + wn * 32 + nf * 8 + 2 * tg;
                *reinterpret_cast<float2*>(Co + (size_t)r1 * DD + col) =
                    make_float2(acc[mf][nf][0] * s1v[mf], acc[mf][nf][1] * s1v[mf]);
                *reinterpret_cast<float2*>(Co + (size_t)r2 * DD + col) =
                    make_float2(acc[mf][nf][2] * s2v[mf], acc[mf][nf][3] * s2v[mf]);
            }
        }
    } else {
        // write rounded Mh and accumulate m2 of the ROUNDED values
        if (tid < 128) s_red[tid] = 0.0f;
        __syncthreads();
        __half* Mo = g_Mh + (size_t)b * SS * DD;
#pragma unroll
        for (int mf = 0; mf < 4; ++mf) {
            int r1 = m0 + wm * 64 + mf * 16 + g;
            int r2 = r1 + 8;
            float a1s = 0.0f, a2s = 0.0f;
#pragma unroll
            for (int nf = 0; nf < 4; ++nf) {
                int col = n0 + wn * 32 + nf * 8 + 2 * tg;
                __half2 h1 = __floats2half2_rn(acc[mf][nf][0] * s1v[mf],
                                               acc[mf][nf][1] * s1v[mf]);
                __half2 h2 = __floats2half2_rn(acc[mf][nf][2] * s2v[mf],
                                               acc[mf][nf][3] * s2v[mf]);
                *reinterpret_cast<__half2*>(Mo + (size_t)r1 * DD + col) = h1;
                *reinterpret_cast<__half2*>(Mo + (size_t)r2 * DD + col) = h2;
                float2 f1 = __half22float2(h1), f2 = __half22float2(h2);
                a1s += f1.x * f1.x + f1.y * f1.y;
                a2s += f2.x * f2.x + f2.y * f2.y;
            }
            a1s += __shfl_xor_sync(0xffffffffu, a1s, 1);
            a1s += __shfl_xor_sync(0xffffffffu, a1s, 2);
            a2s += __shfl_xor_sync(0xffffffffu, a2s, 1);
            a2s += __shfl_xor_sync(0xffffffffu, a2s, 2);
            if (tg == 0) {
                atomicAdd(&s_red[r1 - m0], a1s);
                atomicAdd(&s_red[r2 - m0], a2s);
            }
        }
        __syncthreads();
        if (tid < 128)
            g_m2part[blockIdx.x][b * SS + m0 + tid] = s_red[tid];
    }
}

// ---------------------------------------------------------------------------
// W[i,j] = fp16(Ah[i,j]/(sqrt(max(m2[i]+v2[j]-2*Mh_i.Vh_j,0))+0.01));
// writes per-j-block l1 partials (no atomics on gmem).
// ---------------------------------------------------------------------------
__global__ void __launch_bounds__(NTHREADS, 2)
wdist_tc() {
    extern __shared__ uint32_t dyn[];
    float* s_red = (float*)((char*)dyn + SMEM_PIPE);
    int tid = threadIdx.x;
    int wid = tid >> 5, lane = tid & 31;
    int wm = wid >> 2, wn = wid & 3;
    int g = lane >> 2, tg = lane & 3;
    int q = lane >> 3, lr = lane & 7;
    int b = blockIdx.z;
    int j0 = blockIdx.x * 128, i0 = blockIdx.y * 128;
    const __half* Mp = g_Mh + (size_t)b * SS * DD;
    const __half* Vp = g_Vh + (size_t)b * SS * DD;
    const __half* Ap = g_Ah + (size_t)b * SS * SS;
    __half* Wp = g_W + (size_t)b * SS * SS;
    const float* v2p = g_v2 + b * SS;

    uint32_t aoff[4], boff[2];
#pragma unroll
    for (int mf = 0; mf < 4; ++mf)
        aoff[mf] = ((wm * 64 + mf * 16 + (q & 1) * 8 + lr) * LDSH + (q >> 1) * 8) * 2;
#pragma unroll
    for (int p = 0; p < 2; ++p)
        boff[p] = ((wn * 32 + p * 16 + (q >> 1) * 8 + lr) * LDSH + (q & 1) * 8) * 2;

    float acc[4][4][4];
#pragma unroll
    for (int i = 0; i < 4; ++i)
#pragma unroll
        for (int j = 0; j < 4; ++j)
#pragma unroll
            for (int e = 0; e < 4; ++e) acc[i][j][e] = 0.0f;

    mainloop(Mp, Vp, DD, DD, DD / KC, i0, j0, dyn, acc, tid, aoff, boff);

    // cooperative m2 gather (4 partials per row)
    if (tid < 128) {
        float s = 0.0f;
#pragma unroll
        for (int p = 0; p < 4; ++p) s += g_m2part[p][b * SS + i0 + tid];
        s_red[tid] = s;
    }
    __syncthreads();
    float m21v[4], m22v[4];
#pragma unroll
    for (int mf = 0; mf < 4; ++mf) {
        int rr = wm * 64 + mf * 16 + g;
        m21v[mf] = s_red[rr];
        m22v[mf] = s_red[rr + 8];
    }
    __syncthreads();
    if (tid < 128) s_red[tid] = 0.0f;
    __syncthreads();

#pragma unroll
    for (int mf = 0; mf < 4; ++mf) {
        int r1 = i0 + wm * 64 + mf * 16 + g;
        int r2 = r1 + 8;
        float rs1 = 0.0f, rs2 = 0.0f;
#pragma unroll
        for (int nf = 0; nf < 4; ++nf) {
            int jj = j0 + wn * 32 + nf * 8 + 2 * tg;
            float v2a = v2p[jj], v2b = v2p[jj + 1];
            float2 a1 = __half22float2(
                *reinterpret_cast<const __half2*>(Ap + (size_t)r1 * SS + jj));
            float2 a2 = __half22float2(
                *reinterpret_cast<const __half2*>(Ap + (size_t)r2 * SS + jj));
            float d;
            d = sqrtf(fmaxf(m21v[mf] + v2a - 2.0f * acc[mf][nf][0], 0.0f));
            float w0 = a1.x * __frcp_rn(d + 0.01f);
            d = sqrtf(fmaxf(m21v[mf] + v2b - 2.0f * acc[mf][nf][1], 0.0f));
            float w1 = a1.y * __frcp_rn(d + 0.01f);
            d = sqrtf(fmaxf(m22v[mf] + v2a - 2.0f * acc[mf][nf][2], 0.0f));
            float w2 = a2.x * __frcp_rn(d + 0.01f);
            d = sqrtf(fmaxf(m22v[mf] + v2b - 2.0f * acc[mf][nf][3], 0.0f));
            float w3 = a2.y * __frcp_rn(d + 0.01f);
            __half2 h1 = __floats2half2_rn(w0, w1);
            __half2 h2 = __floats2half2_rn(w2, w3);
            float2 f1 = __half22float2(h1), f2 = __half22float2(h2);
            rs1 += fabsf(f1.x) + fabsf(f1.y);
            rs2 += fabsf(f2.x) + fabsf(f2.y);
            *reinterpret_cast<__half2*>(Wp + (size_t)r1 * SS + jj) = h1;
            *reinterpret_cast<__half2*>(Wp + (size_t)r2 * SS + jj) = h2;
        }
        rs1 += __shfl_xor_sync(0xffffffffu, rs1, 1);
        rs1 += __shfl_xor_sync(0xffffffffu, rs1, 2);
        rs2 += __shfl_xor_sync(0xffffffffu, rs2, 1);
        rs2 += __shfl_xor_sync(0xffffffffu, rs2, 2);
        if (tg == 0) {
            atomicAdd(&s_red[i0 + wm * 64 + mf * 16 + g - i0], rs1);
            atomicAdd(&s_red[wm * 64 + mf * 16 + g + 8], rs2);
        }
    }
    __syncthreads();
    if (tid < 128)
        g_l1part[blockIdx.x][b * SS + i0 + tid] = s_red[tid];
}

// ---------------------------------------------------------------------------
extern "C" void kernel_launch(void* const* d_in, const int* in_sizes, int n_in,
                              void* d_out, int out_size) {
    const float* A = (const float*)d_in[0];  // (4, 2048, 2048)
    const float* V = (const float*)d_in[1];  // (4, 2048, 512)
    float* M = (float*)d_out;                // (4, 2048, 512)

    cudaFuncSetAttribute(gemm_tc, cudaFuncAttributeMaxDynamicSharedMemorySize, SMEM_DYN);
    cudaFuncSetAttribute(wdist_tc, cudaFuncAttributeMaxDynamicSharedMemorySize, SMEM_DYN);

    __half* g_Ah_p;  cudaGetSymbolAddress((void**)&g_Ah_p, g_Ah);
    __half* g_Vh_p;  cudaGetSymbolAddress((void**)&g_Vh_p, g_Vh);

    dim3 ggrid(DD / 128, SS / 128, NB);  // (4, 16, 4)
    dim3 wgrid(SS / 128, SS / 128, NB);  // (16, 16, 4)

    int nA4 = NB * SS * SS / 4;
    // A rounding split into two launches so launch #5 is gemm_tc (ncu -s 5)
    round_kernel<<<1024, 256>>>(A, g_Ah_p, nA4 / 2);
    round_kernel<<<1024, 256>>>(A + (size_t)nA4 / 2 * 4,
                                g_Ah_p + (size_t)nA4 / 2 * 4, nA4 / 2);
    round_kernel<<<512, 256>>>(V, g_Vh_p, NB * SS * DD / 4);
    transpose_kernel<<<dim3(DD / 32, SS / 32, NB), 256>>>(V);
    rownorm_kernel<<<NB * SS, 128>>>(g_Vh_p);
    gemm_tc<<<ggrid, NTHREADS, SMEM_DYN>>>(M, 0, 0, 0);   // launch #5: profiled
    for (int it = 0; it < 3; ++it) {
        wdist_tc<<<wgrid, NTHREADS, SMEM_DYN>>>();
        gemm_tc<<<ggrid, NTHREADS, SMEM_DYN>>>(M, 1, 1, it == 2);
    }
}

// round 13
// speedup vs baseline: 3.0723x; 1.1053x over previous
#include <cuda_runtime.h>
#include <cuda_fp16.h>
#include <math.h>
#include <stdint.h>

#define SS 2048
#define DD 512
#define NB 4
#define KC 64
#define NTHREADS 256                    // 8 warps, 2x4 grid, warp tile 64x32
#define LDSH 72                         // smem row stride in halves (144 B)
#define XTILE_BYTES (128 * LDSH * 2)    // 18432
#define STAGE_BYTES (2 * XTILE_BYTES)   // 36864
#define NSTAGE 3
#define SMEM_PIPE (NSTAGE * STAGE_BYTES) // 110592
#define SMEM_DYN (SMEM_PIPE + 512)

// ---------------- scratch (allocation-free device globals, fp16) ----------
__device__ __half g_W[(size_t)NB * SS * SS];    // 32 MB weight matrix
__device__ __half g_Ah[(size_t)NB * SS * SS];   // 32 MB rounded A
__device__ __half g_Vh[(size_t)NB * SS * DD];   // 8 MB rounded V
__device__ __half g_VTh[(size_t)NB * DD * SS];  // 8 MB rounded V^T [d][s]
__device__ __half g_Mh[(size_t)NB * SS * DD];   // 8 MB rounded M
__device__ float g_v2[NB * SS];
__device__ float g_m2part[4][NB * SS];          // per-n0-block partial |M|^2
__device__ float g_l1part[16][NB * SS];         // per-j-block partial l1 sums

// ---------------- helpers ----------------
__device__ __forceinline__ uint32_t smem_u32(const void* p) {
    uint32_t a;
    asm("{ .reg .u64 t; cvta.to.shared.u64 t, %1; cvt.u32.u64 %0, t; }"
        : "=r"(a) : "l"(p));
    return a;
}
__device__ __forceinline__ void cp16(uint32_t saddr, const void* gaddr) {
    asm volatile("cp.async.cg.shared.global [%0], [%1], 16;"
                 :: "r"(saddr), "l"(gaddr) : "memory");
}
__device__ __forceinline__ void cp_commit() {
    asm volatile("cp.async.commit_group;" ::: "memory");
}
template <int N>
__device__ __forceinline__ void cp_wait() {
    asm volatile("cp.async.wait_group %0;" :: "n"(N) : "memory");
}
__device__ __forceinline__ void ldsm4(uint32_t* r, uint32_t addr) {
    asm volatile("ldmatrix.sync.aligned.m8n8.x4.shared.b16 {%0,%1,%2,%3}, [%4];"
                 : "=r"(r[0]), "=r"(r[1]), "=r"(r[2]), "=r"(r[3]) : "r"(addr));
}
__device__ __forceinline__ void mma_f16(float* c, const uint32_t* a, const uint32_t* b) {
    asm volatile(
        "mma.sync.aligned.m16n8k16.row.col.f32.f16.f16.f32 "
        "{%0,%1,%2,%3}, {%4,%5,%6,%7}, {%8,%9}, {%0,%1,%2,%3};"
        : "+f"(c[0]), "+f"(c[1]), "+f"(c[2]), "+f"(c[3])
        : "r"(a[0]), "r"(a[1]), "r"(a[2]), "r"(a[3]), "r"(b[0]), "r"(b[1]));
}

// ---------------------------------------------------------------------------
// Issue one stage: 128x64 fp16 X tile + Y tile via cp.async. 8x16B per thread.
// ---------------------------------------------------------------------------
__device__ __forceinline__ void issue_stage(const __half* __restrict__ X,
                                            const __half* __restrict__ Y,
                                            int ldx, int ldy, int m0, int n0,
                                            int k0, uint32_t sbuf, int tid) {
#pragma unroll
    for (int p = 0; p < 4; ++p) {
        int idx = tid + p * NTHREADS;
        int row = idx >> 3, q = idx & 7;
        cp16(sbuf + (row * LDSH + q * 8) * 2,
             X + (size_t)(m0 + row) * ldx + k0 + q * 8);
    }
    uint32_t ybuf = sbuf + XTILE_BYTES;
#pragma unroll
    for (int p = 0; p < 4; ++p) {
        int idx = tid + p * NTHREADS;
        int row = idx >> 3, q = idx & 7;
        cp16(ybuf + (row * LDSH + q * 8) * 2,
             Y + (size_t)(n0 + row) * ldy + k0 + q * 8);
    }
    cp_commit();
}

// ---------------------------------------------------------------------------
// One KC=64 chunk: 4 k16 slices. Warp tile 64x32: 4 mf x 4 nf.
// ---------------------------------------------------------------------------
__device__ __forceinline__ void compute_chunk(uint32_t sb, float acc[4][4][4],
                                              const uint32_t* aoff,
                                              const uint32_t* boff) {
    uint32_t ys = sb + XTILE_BYTES;
#pragma unroll
    for (int ks = 0; ks < 4; ++ks) {
        uint32_t kb = ks * 16 * 2;
        uint32_t af[4][4], bf[4][2];
#pragma unroll
        for (int mf = 0; mf < 4; ++mf) ldsm4(af[mf], sb + aoff[mf] + kb);
#pragma unroll
        for (int p = 0; p < 2; ++p) {
            uint32_t r[4];
            ldsm4(r, ys + boff[p] + kb);
            bf[2 * p][0] = r[0];
            bf[2 * p][1] = r[1];
            bf[2 * p + 1][0] = r[2];
            bf[2 * p + 1][1] = r[3];
        }
#pragma unroll
        for (int mf = 0; mf < 4; ++mf)
#pragma unroll
            for (int nf = 0; nf < 4; ++nf)
                mma_f16(acc[mf][nf], af[mf], bf[nf]);
    }
}

// ---------------------------------------------------------------------------
// 3-buffer cp.async mainloop (prefetch depth 2, 1 sync/chunk).
// ---------------------------------------------------------------------------
__device__ __forceinline__ void mainloop(const __half* X, const __half* Y,
                                         int ldx, int ldy, int nch,
                                         int m0, int n0, uint32_t* dyn,
                                         float acc[4][4][4], int tid,
                                         const uint32_t* aoff,
                                         const uint32_t* boff) {
    uint32_t sb = smem_u32(dyn);
    issue_stage(X, Y, ldx, ldy, m0, n0, 0, sb, tid);
    issue_stage(X, Y, ldx, ldy, m0, n0, KC, sb + STAGE_BYTES, tid);
    for (int ch = 0; ch < nch; ++ch) {
        cp_wait<1>();
        __syncthreads();
        if (ch + 2 < nch)
            issue_stage(X, Y, ldx, ldy, m0, n0, (ch + 2) * KC,
                        sb + ((ch + 2) % NSTAGE) * STAGE_BYTES, tid);
        else
            cp_commit();
        compute_chunk(sb + (ch % NSTAGE) * STAGE_BYTES, acc, aoff, boff);
    }
}

// ---------------------------------------------------------------------------
// Elementwise round fp32 -> fp16 (grid-stride, float4 in).
// ---------------------------------------------------------------------------
__global__ void round_kernel(const float* __restrict__ in, __half* __restrict__ out,
                             int n4) {
    int i = blockIdx.x * blockDim.x + threadIdx.x;
    int stride = gridDim.x * blockDim.x;
    for (; i < n4; i += stride) {
        float4 v = reinterpret_cast<const float4*>(in)[i];
        __half2* o = reinterpret_cast<__half2*>(out) + 2 * i;
        o[0] = __floats2half2_rn(v.x, v.y);
        o[1] = __floats2half2_rn(v.z, v.w);
    }
}

// ---------------------------------------------------------------------------
// Fused V prep: g_Vh = round(V); g_VTh[d][s] = round(V[s][d]); g_v2 = row |.|^2
// One block per (32 s-rows, batch); loops over d in 32-chunks.
// ---------------------------------------------------------------------------
__global__ void prepV_kernel(const float* __restrict__ V) {
    __shared__ float t[32][33];
    int b = blockIdx.y;
    int s0 = blockIdx.x * 32;
    const float* Vp = V + (size_t)b * SS * DD;
    __half* Vh = g_Vh + (size_t)b * SS * DD;
    __half* Tp = g_VTh + (size_t)b * DD * SS;
    int tx = threadIdx.x & 31, ty = threadIdx.x >> 5;  // tx: d-lane, ty: s-row base
    float vsum[4] = {0.f, 0.f, 0.f, 0.f};
    for (int dt = 0; dt < DD / 32; ++dt) {
#pragma unroll
        for (int j = 0; j < 4; ++j) {
            int i = ty + 8 * j;  // s-row within tile
            float v = Vp[(size_t)(s0 + i) * DD + dt * 32 + tx];
            __half h = __float2half_rn(v);
            float vr = __half2float(h);
            t[i][tx] = vr;
            vsum[j] += vr * vr;
            Vh[(size_t)(s0 + i) * DD + dt * 32 + tx] = h;
        }
        __syncthreads();
#pragma unroll
        for (int j = 0; j < 4; ++j) {
            int i = ty + 8 * j;  // d-row within tile
            Tp[(size_t)(dt * 32 + i) * SS + s0 + tx] = __float2half_rn(t[tx][i]);
        }
        __syncthreads();
    }
#pragma unroll
    for (int j = 0; j < 4; ++j) {
#pragma unroll
        for (int o = 16; o > 0; o >>= 1)
            vsum[j] += __shfl_down_sync(0xffffffffu, vsum[j], o);
        if (tx == 0) g_v2[b * SS + s0 + ty + 8 * j] = vsum[j];
    }
}

// ---------------------------------------------------------------------------
// GEMM: out[m,n] = scale(m) * sum_k X[m,k]*VTh[n,k]   (N = DD = 512)
// ---------------------------------------------------------------------------
__global__ void __launch_bounds__(NTHREADS, 2)
gemm_tc(float* __restrict__ C, int use_w, int use_l1, int final_out) {
    extern __shared__ uint32_t dyn[];
    float* s_red = (float*)((char*)dyn + SMEM_PIPE);
    int tid = threadIdx.x;
    int wid = tid >> 5, lane = tid & 31;
    int wm = wid >> 2, wn = wid & 3;
    int g = lane >> 2, tg = lane & 3;
    int q = lane >> 3, lr = lane & 7;
    int b = blockIdx.z;
    int n0 = blockIdx.x * 128, m0 = blockIdx.y * 128;
    const __half* X = (use_w ? g_W : g_Ah) + (size_t)b * SS * SS;
    const __half* Y = g_VTh + (size_t)b * DD * SS;

    uint32_t aoff[4], boff[2];
#pragma unroll
    for (int mf = 0; mf < 4; ++mf)
        aoff[mf] = ((wm * 64 + mf * 16 + (q & 1) * 8 + lr) * LDSH + (q >> 1) * 8) * 2;
#pragma unroll
    for (int p = 0; p < 2; ++p)
        boff[p] = ((wn * 32 + p * 16 + (q >> 1) * 8 + lr) * LDSH + (q & 1) * 8) * 2;

    float acc[4][4][4];
#pragma unroll
    for (int i = 0; i < 4; ++i)
#pragma unroll
        for (int j = 0; j < 4; ++j)
#pragma unroll
            for (int e = 0; e < 4; ++e) acc[i][j][e] = 0.0f;

    mainloop(X, Y, SS, SS, SS / KC, m0, n0, dyn, acc, tid, aoff, boff);

    float s1v[4], s2v[4];
    if (use_l1) {
        if (tid < 128) {
            float s = 0.0f;
#pragma unroll
            for (int p = 0; p < 16; ++p) s += g_l1part[p][b * SS + m0 + tid];
            s_red[tid] = s;
        }
        __syncthreads();
#pragma unroll
        for (int mf = 0; mf < 4; ++mf) {
            int rr = wm * 64 + mf * 16 + g;
            s1v[mf] = 1.0f / fmaxf(s_red[rr], 1e-12f);
            s2v[mf] = 1.0f / fmaxf(s_red[rr + 8], 1e-12f);
        }
        __syncthreads();
    } else {
#pragma unroll
        for (int mf = 0; mf < 4; ++mf) { s1v[mf] = 1.0f; s2v[mf] = 1.0f; }
    }

    if (final_out) {
        float* Co = C + (size_t)b * SS * DD;
#pragma unroll
        for (int mf = 0; mf < 4; ++mf) {
            int r1 = m0 + wm * 64 + mf * 16 + g;
            int r2 = r1 + 8;
#pragma unroll
            for (int nf = 0; nf < 4; ++nf) {
                int col = n0 + wn * 32 + nf * 8 + 2 * tg;
                *reinterpret_cast<float2*>(Co + (size_t)r1 * DD + col) =
                    make_float2(acc[mf][nf][0] * s1v[mf], acc[mf][nf][1] * s1v[mf]);
                *reinterpret_cast<float2*>(Co + (size_t)r2 * DD + col) =
                    make_float2(acc[mf][nf][2] * s2v[mf], acc[mf][nf][3] * s2v[mf]);
            }
        }
    } else {
        if (tid < 128) s_red[tid] = 0.0f;
        __syncthreads();
        __half* Mo = g_Mh + (size_t)b * SS * DD;
#pragma unroll
        for (int mf = 0; mf < 4; ++mf) {
            int r1 = m0 + wm * 64 + mf * 16 + g;
            int r2 = r1 + 8;
            float a1s = 0.0f, a2s = 0.0f;
#pragma unroll
            for (int nf = 0; nf < 4; ++nf) {
                int col = n0 + wn * 32 + nf * 8 + 2 * tg;
                __half2 h1 = __floats2half2_rn(acc[mf][nf][0] * s1v[mf],
                                               acc[mf][nf][1] * s1v[mf]);
                __half2 h2 = __floats2half2_rn(acc[mf][nf][2] * s2v[mf],
                                               acc[mf][nf][3] * s2v[mf]);
                *reinterpret_cast<__half2*>(Mo + (size_t)r1 * DD + col) = h1;
                *reinterpret_cast<__half2*>(Mo + (size_t)r2 * DD + col) = h2;
                float2 f1 = __half22float2(h1), f2 = __half22float2(h2);
                a1s += f1.x * f1.x + f1.y * f1.y;
                a2s += f2.x * f2.x + f2.y * f2.y;
            }
            a1s += __shfl_xor_sync(0xffffffffu, a1s, 1);
            a1s += __shfl_xor_sync(0xffffffffu, a1s, 2);
            a2s += __shfl_xor_sync(0xffffffffu, a2s, 1);
            a2s += __shfl_xor_sync(0xffffffffu, a2s, 2);
            if (tg == 0) {
                atomicAdd(&s_red[wm * 64 + mf * 16 + g], a1s);
                atomicAdd(&s_red[wm * 64 + mf * 16 + g + 8], a2s);
            }
        }
        __syncthreads();
        if (tid < 128)
            g_m2part[blockIdx.x][b * SS + m0 + tid] = s_red[tid];
    }
}

// ---------------------------------------------------------------------------
// W[i,j] = fp16(Ah[i,j]/(sqrt(max(m2[i]+v2[j]-2*Mh_i.Vh_j,0))+0.01));
// writes per-j-block l1 partials.
// ---------------------------------------------------------------------------
__global__ void __launch_bounds__(NTHREADS, 2)
wdist_tc() {
    extern __shared__ uint32_t dyn[];
    float* s_red = (float*)((char*)dyn + SMEM_PIPE);
    int tid = threadIdx.x;
    int wid = tid >> 5, lane = tid & 31;
    int wm = wid >> 2, wn = wid & 3;
    int g = lane >> 2, tg = lane & 3;
    int q = lane >> 3, lr = lane & 7;
    int b = blockIdx.z;
    int j0 = blockIdx.x * 128, i0 = blockIdx.y * 128;
    const __half* Mp = g_Mh + (size_t)b * SS * DD;
    const __half* Vp = g_Vh + (size_t)b * SS * DD;
    const __half* Ap = g_Ah + (size_t)b * SS * SS;
    __half* Wp = g_W + (size_t)b * SS * SS;
    const float* v2p = g_v2 + b * SS;

    uint32_t aoff[4], boff[2];
#pragma unroll
    for (int mf = 0; mf < 4; ++mf)
        aoff[mf] = ((wm * 64 + mf * 16 + (q & 1) * 8 + lr) * LDSH + (q >> 1) * 8) * 2;
#pragma unroll
    for (int p = 0; p < 2; ++p)
        boff[p] = ((wn * 32 + p * 16 + (q >> 1) * 8 + lr) * LDSH + (q & 1) * 8) * 2;

    float acc[4][4][4];
#pragma unroll
    for (int i = 0; i < 4; ++i)
#pragma unroll
        for (int j = 0; j < 4; ++j)
#pragma unroll
            for (int e = 0; e < 4; ++e) acc[i][j][e] = 0.0f;

    mainloop(Mp, Vp, DD, DD, DD / KC, i0, j0, dyn, acc, tid, aoff, boff);

    if (tid < 128) {
        float s = 0.0f;
#pragma unroll
        for (int p = 0; p < 4; ++p) s += g_m2part[p][b * SS + i0 + tid];
        s_red[tid] = s;
    }
    __syncthreads();
    float m21v[4], m22v[4];
#pragma unroll
    for (int mf = 0; mf < 4; ++mf) {
        int rr = wm * 64 + mf * 16 + g;
        m21v[mf] = s_red[rr];
        m22v[mf] = s_red[rr + 8];
    }
    __syncthreads();
    if (tid < 128) s_red[tid] = 0.0f;
    __syncthreads();

#pragma unroll
    for (int mf = 0; mf < 4; ++mf) {
        int r1 = i0 + wm * 64 + mf * 16 + g;
        int r2 = r1 + 8;
        float rs1 = 0.0f, rs2 = 0.0f;
#pragma unroll
        for (int nf = 0; nf < 4; ++nf) {
            int jj = j0 + wn * 32 + nf * 8 + 2 * tg;
            float v2a = v2p[jj], v2b = v2p[jj + 1];
            float2 a1 = __half22float2(
                *reinterpret_cast<const __half2*>(Ap + (size_t)r1 * SS + jj));
            float2 a2 = __half22float2(
                *reinterpret_cast<const __half2*>(Ap + (size_t)r2 * SS + jj));
            float d;
            d = sqrtf(fmaxf(m21v[mf] + v2a - 2.0f * acc[mf][nf][0], 0.0f));
            float w0 = a1.x * __frcp_rn(d + 0.01f);
            d = sqrtf(fmaxf(m21v[mf] + v2b - 2.0f * acc[mf][nf][1], 0.0f));
            float w1 = a1.y * __frcp_rn(d + 0.01f);
            d = sqrtf(fmaxf(m22v[mf] + v2a - 2.0f * acc[mf][nf][2], 0.0f));
            float w2 = a2.x * __frcp_rn(d + 0.01f);
            d = sqrtf(fmaxf(m22v[mf] + v2b - 2.0f * acc[mf][nf][3], 0.0f));
            float w3 = a2.y * __frcp_rn(d + 0.01f);
            __half2 h1 = __floats2half2_rn(w0, w1);
            __half2 h2 = __floats2half2_rn(w2, w3);
            float2 f1 = __half22float2(h1), f2 = __half22float2(h2);
            rs1 += fabsf(f1.x) + fabsf(f1.y);
            rs2 += fabsf(f2.x) + fabsf(f2.y);
            *reinterpret_cast<__half2*>(Wp + (size_t)r1 * SS + jj) = h1;
            *reinterpret_cast<__half2*>(Wp + (size_t)r2 * SS + jj) = h2;
        }
        rs1 += __shfl_xor_sync(0xffffffffu, rs1, 1);
        rs1 += __shfl_xor_sync(0xffffffffu, rs1, 2);
        rs2 += __shfl_xor_sync(0xffffffffu, rs2, 1);
        rs2 += __shfl_xor_sync(0xffffffffu, rs2, 2);
        if (tg == 0) {
            atomicAdd(&s_red[wm * 64 + mf * 16 + g], rs1);
            atomicAdd(&s_red[wm * 64 + mf * 16 + g + 8], rs2);
        }
    }
    __syncthreads();
    if (tid < 128)
        g_l1part[blockIdx.x][b * SS + i0 + tid] = s_red[tid];
}

// ---------------------------------------------------------------------------
extern "C" void kernel_launch(void* const* d_in, const int* in_sizes, int n_in,
                              void* d_out, int out_size) {
    const float* A = (const float*)d_in[0];  // (4, 2048, 2048)
    const float* V = (const float*)d_in[1];  // (4, 2048, 512)
    float* M = (float*)d_out;                // (4, 2048, 512)

    cudaFuncSetAttribute(gemm_tc, cudaFuncAttributeMaxDynamicSharedMemorySize, SMEM_DYN);
    cudaFuncSetAttribute(wdist_tc, cudaFuncAttributeMaxDynamicSharedMemorySize, SMEM_DYN);

    __half* g_Ah_p;  cudaGetSymbolAddress((void**)&g_Ah_p, g_Ah);

    dim3 ggrid(DD / 128, SS / 128, NB);  // (4, 16, 4)
    dim3 wgrid(SS / 128, SS / 128, NB);  // (16, 16, 4)

    int nA4 = NB * SS * SS / 4;
    round_kernel<<<1024, 256>>>(A, g_Ah_p, nA4 / 2);                     // #1
    round_kernel<<<1024, 256>>>(A + (size_t)nA4 / 2 * 4,
                                g_Ah_p + (size_t)nA4 / 2 * 4, nA4 / 2);  // #2
    prepV_kernel<<<dim3(SS / 32, NB), 256>>>(V);                         // #3
    gemm_tc<<<ggrid, NTHREADS, SMEM_DYN>>>(M, 0, 0, 0);                  // #4 (profiled)
    for (int it = 0; it < 3; ++it) {
        wdist_tc<<<wgrid, NTHREADS, SMEM_DYN>>>();
        gemm_tc<<<ggrid, NTHREADS, SMEM_DYN>>>(M, 1, 1, it == 2);
    }
}